// round 13
// baseline (speedup 1.0000x reference)
#include <cuda_runtime.h>
#include <cuda_fp16.h>
#include <math.h>
#include <stdint.h>

// ---------------------------------------------------------------------------
// Problem constants
// ---------------------------------------------------------------------------
#define HID    512
#define GATES  2048
#define MAXLEN 128
#define BMAX   1024
#define TMAX   (BMAX * 127)
#define K0PAD  192
#define NCTA   128         // persistent LSTM grid (16 nblk x 8 mblk)
#define NGRP   8
#define GRPSZ  16

// chunking
#define CH        64
#define NKT       8
#define AS_STRIDE 72
#define AS_STAGE  (128 * AS_STRIDE)

// hgemm: 64-col K chunks, 3 stages
#define HG_STRIDE 72
#define HG_STAGE  (128 * HG_STRIDE)
#define HG_SMEM   (6 * HG_STAGE * 2)

// ---------------------------------------------------------------------------
// Scratch
// ---------------------------------------------------------------------------
__device__ __half g_feat16[(size_t)TMAX * K0PAD];
__device__ __half g_x1h  [(size_t)TMAX * HID];
__device__ __half g_x2h  [(size_t)TMAX * HID];
__device__ __half g_xp16 [(size_t)TMAX * GATES];
__device__ __half g_We0h [HID * K0PAD];
__device__ __half g_We1h [HID * HID];
__device__ __half g_Wihp [GATES * HID];     // gate-interleaved rows
__device__ __half g_Whhp [GATES * HID];     // gate-interleaved rows
__device__ float  g_bsum [GATES];           // gate-interleaved bih+bhh
__device__ __half g_h0   [BMAX * HID];
__device__ __half g_h1   [BMAX * HID];
__device__ float  g_hf   [BMAX * HID];
__device__ float  g_t0   [BMAX * HID];
__device__ float  g_t1   [BMAX * HID];
__device__ int    g_starts[BMAX];
// dataflow flags: flag[m][j] = steps completed by producer CTA (m, j).
// padded to one 128B line each to avoid cross-producer invalidation.
__device__ volatile unsigned g_flag[NGRP][GRPSZ][32];

// ---------------------------------------------------------------------------
// Helpers
// ---------------------------------------------------------------------------
__device__ __forceinline__ uint32_t smem_u32(const void* p) {
    return (uint32_t)__cvta_generic_to_shared(p);
}
__device__ __forceinline__ void cp_async16(void* dst, const void* src, bool pred) {
    uint32_t d = smem_u32(dst);
    int sz = pred ? 16 : 0;
    asm volatile("cp.async.cg.shared.global [%0], [%1], 16, %2;\n"
                 :: "r"(d), "l"(src), "r"(sz));
}
__device__ __forceinline__ void cp_commit() { asm volatile("cp.async.commit_group;\n"); }
template<int N> __device__ __forceinline__ void cp_wait() {
    asm volatile("cp.async.wait_group %0;\n" :: "n"(N));
}
__device__ __forceinline__ void ldm_x4(uint32_t addr, uint32_t& r0, uint32_t& r1,
                                       uint32_t& r2, uint32_t& r3) {
    asm volatile("ldmatrix.sync.aligned.m8n8.x4.shared.b16 {%0,%1,%2,%3}, [%4];"
                 : "=r"(r0), "=r"(r1), "=r"(r2), "=r"(r3) : "r"(addr));
}
__device__ __forceinline__ void mma16816(float* c, const uint32_t* a, const uint32_t* b) {
    asm volatile("mma.sync.aligned.m16n8k16.row.col.f32.f16.f16.f32 "
                 "{%0,%1,%2,%3}, {%4,%5,%6,%7}, {%8,%9}, {%0,%1,%2,%3};"
                 : "+f"(c[0]), "+f"(c[1]), "+f"(c[2]), "+f"(c[3])
                 : "r"(a[0]), "r"(a[1]), "r"(a[2]), "r"(a[3]), "r"(b[0]), "r"(b[1]));
}
__device__ __forceinline__ float fast_sigmoid(float x) {
    return __fdividef(1.f, 1.f + __expf(-x));
}
__device__ __forceinline__ float fast_tanh(float x) {
    float xc = fminf(fmaxf(x, -8.f), 8.f);
    float e = __expf(2.f * xc);
    return __fdividef(e - 1.f, e + 1.f);
}

// ---------------------------------------------------------------------------
// setup: scan (launch 1) + merged prep (launch 2)
// ---------------------------------------------------------------------------
__global__ void scan_starts_kernel(const int* __restrict__ sizes, int* __restrict__ starts, int B) {
    __shared__ int s[BMAX];
    int tid = threadIdx.x;
    if (tid < B) s[tid] = sizes[tid];
    __syncthreads();
    if (tid == 0) {
        int acc = 0;
        for (int i = 0; i < B; i++) { starts[i] = acc; acc += s[i]; }
    }
}

__global__ void prep_kernel(const float* __restrict__ feat,
                            const float* __restrict__ We0, const float* __restrict__ We1,
                            const float* __restrict__ Wih, const float* __restrict__ Whh,
                            const float* __restrict__ bih, const float* __restrict__ bhh,
                            int T, int K0, int nb_feat)
{
    int b = blockIdx.x, tid = threadIdx.x;
    if (b < nb_feat) {
        int i = b * 256 + tid;
        if (i < T * K0PAD) {
            int r = i / K0PAD, c = i - r * K0PAD;
            g_feat16[i] = __float2half(c < K0 ? feat[(size_t)r * K0 + c] : 0.f);
        }
        return;
    }
    b -= nb_feat;
    if (b < 384) {
        int i = b * 256 + tid;
        int r = i / K0PAD, c = i - r * K0PAD;
        g_We0h[i] = __float2half(c < K0 ? We0[(size_t)r * K0 + c] : 0.f);
        return;
    }
    b -= 384;
    if (b < 1024) {
        int i = b * 256 + tid;
        g_We1h[i] = __float2half(We1[i]);
        return;
    }
    b -= 1024;
    if (b < 4096) {
        int i = b * 256 + tid;
        int r = i >> 9, c = i & 511;
        int g = r >> 9, hid = r & 511;
        g_Wihp[(size_t)(hid * 4 + g) * HID + c] = __float2half(Wih[i]);
        return;
    }
    b -= 4096;
    if (b < 4096) {
        int i = b * 256 + tid;
        int r = i >> 9, c = i & 511;
        int g = r >> 9, hid = r & 511;
        g_Whhp[(size_t)(hid * 4 + g) * HID + c] = __float2half(Whh[i]);
        return;
    }
    b -= 4096;
    if (b < 8) {
        int o = b * 256 + tid;
        int hid = o >> 2, g = o & 3;
        g_bsum[o] = bih[g * HID + hid] + bhh[g * HID + hid];
        return;
    }
    b -= 8;
    if (b < 16) {                         // zero dataflow flags (graph-replay safe)
        int i = b * 256 + tid;
        if (i < NGRP * GRPSZ * 32)
            (&g_flag[0][0][0])[i] = 0;
        return;
    }
    b -= 16;
    {
        int i = b * 256 + tid;
        g_h0[i] = __float2half(0.f);
    }
}

// ---------------------------------------------------------------------------
// fp16 NT GEMM (encoder / xproj): 64-col K chunks, ONE sync per chunk,
// 3-stage cp.async ring, 2 CTAs/SM.
// ---------------------------------------------------------------------------
template<bool RELU, bool HAS_BIAS>
__global__ __launch_bounds__(256, 2)
void hgemm_nt(const __half* __restrict__ A, const __half* __restrict__ B,
              const float* __restrict__ bias, __half* __restrict__ Cout,
              int M, int N, int K)
{
    extern __shared__ char smem[];
    __half* As = (__half*)smem;                       // [3][128][72]
    __half* Bs = (__half*)(smem + 3 * HG_STAGE * 2);  // [3][128][72]

    const int m0 = blockIdx.y * 128;
    const int n0 = blockIdx.x * 128;
    const int tid = threadIdx.x;
    const int warp = tid >> 5, lane = tid & 31;
    const int wm = (warp & 3) * 32;
    const int wn = (warp >> 2) * 64;

    float acc[2][8][4];
    #pragma unroll
    for (int i = 0; i < 2; i++)
        #pragma unroll
        for (int j = 0; j < 8; j++)
            #pragma unroll
            for (int q = 0; q < 4; q++) acc[i][j][q] = 0.f;

    const int KT = K >> 6;

    auto load_chunk = [&](int c, int s) {
        const int k0 = c << 6;
        for (int i = tid; i < 1024; i += 256) {
            int r = i >> 3, ch = i & 7;
            int gm = m0 + r;
            bool p = gm < M;
            cp_async16(&As[s * HG_STAGE + r * HG_STRIDE + ch * 8],
                       A + (size_t)(p ? gm : 0) * K + k0 + ch * 8, p);
        }
        for (int i = tid; i < 1024; i += 256) {
            int r = i >> 3, ch = i & 7;
            cp_async16(&Bs[s * HG_STAGE + r * HG_STRIDE + ch * 8],
                       B + (size_t)(n0 + r) * K + k0 + ch * 8, true);
        }
        cp_commit();
    };

    load_chunk(0, 0);
    if (KT > 1) load_chunk(1, 1);

    for (int kt = 0; kt < KT; kt++) {
        if (kt + 1 < KT) cp_wait<1>(); else cp_wait<0>();
        __syncthreads();
        if (kt + 2 < KT) load_chunk(kt + 2, (kt + 2) % 3);

        const int stage = kt % 3;
        #pragma unroll
        for (int s = 0; s < 4; s++) {
            uint32_t afrag[2][4];
            #pragma unroll
            for (int mi = 0; mi < 2; mi++) {
                int r = wm + mi * 16 + (lane & 15);
                int c = s * 16 + (lane >> 4) * 8;
                ldm_x4(smem_u32(&As[stage * HG_STAGE + r * HG_STRIDE + c]),
                       afrag[mi][0], afrag[mi][1], afrag[mi][2], afrag[mi][3]);
            }
            uint32_t bfrag[8][2];
            #pragma unroll
            for (int njp = 0; njp < 4; njp++) {
                int g = lane >> 3;
                int nrow = wn + njp * 16 + (g >> 1) * 8 + (lane & 7);
                int c = s * 16 + (g & 1) * 8;
                uint32_t r0, r1, r2, r3;
                ldm_x4(smem_u32(&Bs[stage * HG_STAGE + nrow * HG_STRIDE + c]), r0, r1, r2, r3);
                bfrag[njp * 2][0] = r0; bfrag[njp * 2][1] = r1;
                bfrag[njp * 2 + 1][0] = r2; bfrag[njp * 2 + 1][1] = r3;
            }
            #pragma unroll
            for (int mi = 0; mi < 2; mi++)
                #pragma unroll
                for (int ni = 0; ni < 8; ni++)
                    mma16816(acc[mi][ni], afrag[mi], bfrag[ni]);
        }
    }

    const int r_lo = lane >> 2;
    const int cpair = (lane & 3) * 2;
    #pragma unroll
    for (int mi = 0; mi < 2; mi++) {
        #pragma unroll
        for (int hr = 0; hr < 2; hr++) {
            int gr = m0 + wm + mi * 16 + r_lo + hr * 8;
            if (gr >= M) continue;
            #pragma unroll
            for (int ni = 0; ni < 8; ni++) {
                int gc = n0 + wn + ni * 8 + cpair;
                float v0 = acc[mi][ni][hr * 2 + 0];
                float v1 = acc[mi][ni][hr * 2 + 1];
                if (HAS_BIAS) { v0 += bias[gc]; v1 += bias[gc + 1]; }
                if (RELU) { v0 = fmaxf(v0, 0.f); v1 = fmaxf(v1, 0.f); }
                __half2 hv;
                hv.x = __float2half(v0); hv.y = __float2half(v1);
                *reinterpret_cast<__half2*>(Cout + (size_t)gr * N + gc) = hv;
            }
        }
    }
}

// ---------------------------------------------------------------------------
// Persistent LSTM: 512 threads (16 warps, 32x32 warp tiles).
// Inter-CTA sync = per-producer dataflow flags (wavefront pipelining):
// chunk kt of step t waits only on producers 2kt, 2kt+1 having finished
// step t-1 (flag >= t). Producer (m,j) publishes flag[m][j]=t+1 after its
// h-store of step t.
// ---------------------------------------------------------------------------
#define LSTM_SMEM 212480
#define LNT 512

__global__ __launch_bounds__(LNT, 1)
void lstm_persist(const __half* __restrict__ Whp, const __half* __restrict__ xp,
                  const float* __restrict__ bsum,
                  const int* __restrict__ starts, const int* __restrict__ sizes,
                  __half* __restrict__ hbuf0, __half* __restrict__ hbuf1,
                  float* __restrict__ hf)
{
    extern __shared__ char smem[];
    __half* WhS = (__half*)(smem);
    __half* AS  = (__half*)(smem + 133120);
    __half* xpS = (__half*)(smem + 169984);
    float*  bsS = (float*) (smem + 202752);
    int*    stS = (int*)   (smem + 203264);
    int*    szS = (int*)   (smem + 203776);
    __half* hS  = (__half*)(smem + 204288);

    const int tid  = threadIdx.x;
    const int warp = tid >> 5, lane = tid & 31;
    const int nblk = blockIdx.x & 15, mblk = blockIdx.x >> 4;
    const int n0 = nblk * 128, m0 = mblk * 128;
    const int wm = (warp & 3) * 32;
    const int wn = (warp >> 2) * 32;

    for (int i = tid; i < 128 * 64; i += LNT) {
        int r = i >> 6, ch = i & 63;
        cp_async16(&WhS[r * 520 + ch * 8], Whp + (size_t)(n0 + r) * HID + ch * 8, true);
    }
    cp_commit();
    for (int i = tid; i < 128; i += LNT) {
        bsS[i] = bsum[n0 + i];
        stS[i] = starts[m0 + i];
        szS[i] = sizes[m0 + i];
    }
    cp_wait<0>();
    __syncthreads();

    float creg[2][2][4];
    #pragma unroll
    for (int mi = 0; mi < 2; mi++)
        #pragma unroll
        for (int hr = 0; hr < 2; hr++)
            #pragma unroll
            for (int ni = 0; ni < 4; ni++) creg[mi][hr][ni] = 0.f;

    // prologue: xp(0) + A chunk 0 of step 0 (initial h0 needs no flags)
    for (int i = tid; i < 2048; i += LNT) {
        int rl = i >> 4, ch = i & 15;
        bool pv = 0 < szS[rl];
        cp_async16(&xpS[rl * 128 + ch * 8], xp + (size_t)stS[rl] * GATES + n0 + ch * 8, pv);
    }
    for (int i = tid; i < 1024; i += LNT) {
        int r = i >> 3, ch = i & 7;
        cp_async16(&AS[r * AS_STRIDE + ch * 8], hbuf0 + (size_t)(m0 + r) * HID + ch * 8, true);
    }
    cp_commit();

    for (int t = 0; t < MAXLEN; t++) {
        const __half* hA = (t & 1) ? hbuf1 : hbuf0;
        __half*       hN = (t & 1) ? hbuf0 : hbuf1;

        float acc[2][4][4];
        #pragma unroll
        for (int mi = 0; mi < 2; mi++)
            #pragma unroll
            for (int ni = 0; ni < 4; ni++)
                #pragma unroll
                for (int q = 0; q < 4; q++) acc[mi][ni][q] = 0.f;

        for (int kt = 0; kt < NKT; kt++) {
            cp_wait<0>();
            // wait for the two producers of chunk kt+1 (h of step t-1);
            // trivially satisfied at t=0 (flags start at 0).
            if (kt < NKT - 1 && tid < 2) {
                int p = 2 * (kt + 1) + tid;
                while ((int)g_flag[mblk][p][0] < t) { }
            }
            __syncthreads();
            if (kt < NKT - 1) {
                const int k0 = (kt + 1) * CH;
                const int stg = (kt + 1) & 1;
                for (int i = tid; i < 1024; i += LNT) {
                    int r = i >> 3, ch = i & 7;
                    cp_async16(&AS[stg * AS_STAGE + r * AS_STRIDE + ch * 8],
                               hA + (size_t)(m0 + r) * HID + k0 + ch * 8, true);
                }
                cp_commit();
            }
            const int stage = kt & 1;
            #pragma unroll
            for (int s = 0; s < 4; s++) {
                const int ks = kt * 4 + s;
                uint32_t afrag[2][4];
                #pragma unroll
                for (int mi = 0; mi < 2; mi++) {
                    int r = wm + mi * 16 + (lane & 15);
                    int c = s * 16 + (lane >> 4) * 8;
                    ldm_x4(smem_u32(&AS[stage * AS_STAGE + r * AS_STRIDE + c]),
                           afrag[mi][0], afrag[mi][1], afrag[mi][2], afrag[mi][3]);
                }
                uint32_t bfrag[4][2];
                #pragma unroll
                for (int njp = 0; njp < 2; njp++) {
                    int g = lane >> 3;
                    int nrow = wn + njp * 16 + (g >> 1) * 8 + (lane & 7);
                    int c = ks * 16 + (g & 1) * 8;
                    uint32_t r0, r1, r2, r3;
                    ldm_x4(smem_u32(&WhS[nrow * 520 + c]), r0, r1, r2, r3);
                    bfrag[njp * 2][0] = r0; bfrag[njp * 2][1] = r1;
                    bfrag[njp * 2 + 1][0] = r2; bfrag[njp * 2 + 1][1] = r3;
                }
                #pragma unroll
                for (int mi = 0; mi < 2; mi++)
                    #pragma unroll
                    for (int ni = 0; ni < 4; ni++)
                        mma16816(acc[mi][ni], afrag[mi], bfrag[ni]);
            }
        }

        // ---- fused LSTM epilogue (fast-math) ----
        const int hlq = (lane & 3) >> 1;
        const int rbase = wm + (lane >> 2);
        #pragma unroll
        for (int mi = 0; mi < 2; mi++) {
            #pragma unroll
            for (int hr = 0; hr < 2; hr++) {
                const int rl = rbase + mi * 16 + hr * 8;
                #pragma unroll
                for (int ni = 0; ni < 4; ni++) {
                    float v0 = acc[mi][ni][hr * 2 + 0];
                    float v1 = acc[mi][ni][hr * 2 + 1];
                    float w0 = __shfl_xor_sync(0xffffffffu, v0, 1);
                    float w1 = __shfl_xor_sync(0xffffffffu, v1, 1);
                    if ((lane & 1) == 0) {
                        const int hl = ((wn + ni * 8) >> 2) + hlq;
                        float gi = v0 + bsS[hl * 4 + 0];
                        float gf = v1 + bsS[hl * 4 + 1];
                        float gg = w0 + bsS[hl * 4 + 2];
                        float go = w1 + bsS[hl * 4 + 3];
                        if (t < szS[rl]) {
                            uint2 xv = *reinterpret_cast<const uint2*>(&xpS[rl * 128 + hl * 4]);
                            __half2 x01 = *reinterpret_cast<__half2*>(&xv.x);
                            __half2 x23 = *reinterpret_cast<__half2*>(&xv.y);
                            gi += __half2float(x01.x);
                            gf += __half2float(x01.y);
                            gg += __half2float(x23.x);
                            go += __half2float(x23.y);
                        }
                        float is = fast_sigmoid(gi);
                        float fs = fast_sigmoid(gf);
                        float gt = fast_tanh(gg);
                        float os = fast_sigmoid(go);
                        float cn = fs * creg[mi][hr][ni] + is * gt;
                        creg[mi][hr][ni] = cn;
                        hS[rl * 32 + hl] = __float2half(os * fast_tanh(cn));
                    }
                }
            }
        }
        __syncthreads();
        for (int i = tid; i < 512; i += LNT) {
            int r = i >> 2, ch = i & 3;
            *reinterpret_cast<uint4*>(hN + (size_t)(m0 + r) * HID + nblk * 32 + ch * 8) =
                *reinterpret_cast<const uint4*>(&hS[r * 32 + ch * 8]);
        }
        if (t == MAXLEN - 1) {
            for (int i = tid; i < 4096; i += LNT) {
                int r = i >> 5, cch = i & 31;
                hf[(size_t)(m0 + r) * HID + nblk * 32 + cch] = __half2float(hS[r * 32 + cch]);
            }
            break;
        }
        __syncthreads();   // all h stores issued before the release below
        if (tid == 0) {
            __threadfence();
            g_flag[mblk][nblk][0] = (unsigned)(t + 1);
        }

        // xp(t+1) prefetch (independent of h) — overlaps producer waits
        for (int i = tid; i < 2048; i += LNT) {
            int rl = i >> 4, ch = i & 15;
            bool pv = (t + 1) < szS[rl];
            cp_async16(&xpS[rl * 128 + ch * 8],
                       xp + (size_t)(stS[rl] + t + 1) * GATES + n0 + ch * 8, pv);
        }
        cp_commit();

        // wait only for producers of chunk 0 of step t+1
        if (tid < 2) {
            while ((int)g_flag[mblk][tid][0] < t + 1) { }
        }
        __syncthreads();

        for (int i = tid; i < 1024; i += LNT) {
            int r = i >> 3, ch = i & 7;
            cp_async16(&AS[r * AS_STRIDE + ch * 8], hN + (size_t)(m0 + r) * HID + ch * 8, true);
        }
        cp_commit();
    }
}

// ---------------------------------------------------------------------------
// fp32 tail GEMM + decoder
// ---------------------------------------------------------------------------
#define BM 64
#define BN 64
#define BK 16
__global__ __launch_bounds__(256) void gemm_nt_kernel(
    const float* __restrict__ A, const float* __restrict__ B,
    const float* __restrict__ bias, const float* __restrict__ R,
    float* __restrict__ C, int M, int N, int K)
{
    __shared__ float As[BK][BM];
    __shared__ float Bs[BK][BN];
    const int m0 = blockIdx.y * BM;
    const int n0 = blockIdx.x * BN;
    const int tid = threadIdx.x;
    const int tx = tid & 15, ty = tid >> 4;
    const int lrow = tid >> 2, lkq = (tid & 3) * 4;
    float acc[4][4] = {};
    for (int k0 = 0; k0 < K; k0 += BK) {
        {
            int gm = m0 + lrow;
            float4 v = make_float4(0.f, 0.f, 0.f, 0.f);
            if (gm < M) v = *reinterpret_cast<const float4*>(A + (size_t)gm * K + k0 + lkq);
            As[lkq + 0][lrow] = v.x; As[lkq + 1][lrow] = v.y;
            As[lkq + 2][lrow] = v.z; As[lkq + 3][lrow] = v.w;
        }
        {
            float4 v = *reinterpret_cast<const float4*>(B + (size_t)(n0 + lrow) * K + k0 + lkq);
            Bs[lkq + 0][lrow] = v.x; Bs[lkq + 1][lrow] = v.y;
            Bs[lkq + 2][lrow] = v.z; Bs[lkq + 3][lrow] = v.w;
        }
        __syncthreads();
        #pragma unroll
        for (int k = 0; k < BK; k++) {
            float4 a = *reinterpret_cast<const float4*>(&As[k][ty * 4]);
            float4 b = *reinterpret_cast<const float4*>(&Bs[k][tx * 4]);
            acc[0][0] += a.x * b.x; acc[0][1] += a.x * b.y; acc[0][2] += a.x * b.z; acc[0][3] += a.x * b.w;
            acc[1][0] += a.y * b.x; acc[1][1] += a.y * b.y; acc[1][2] += a.y * b.z; acc[1][3] += a.y * b.w;
            acc[2][0] += a.z * b.x; acc[2][1] += a.z * b.y; acc[2][2] += a.z * b.z; acc[2][3] += a.z * b.w;
            acc[3][0] += a.w * b.x; acc[3][1] += a.w * b.y; acc[3][2] += a.w * b.z; acc[3][3] += a.w * b.w;
        }
        __syncthreads();
    }
    #pragma unroll
    for (int i = 0; i < 4; i++) {
        int gm = m0 + ty * 4 + i;
        if (gm >= M) continue;
        #pragma unroll
        for (int j = 0; j < 4; j++) {
            int gn = n0 + tx * 4 + j;
            float v = acc[i][j] + bias[gn];
            v = fmaxf(v, 0.f);
            v += R[(size_t)gm * N + gn];
            C[(size_t)gm * N + gn] = v;
        }
    }
}

__global__ void decoder_kernel(const float* __restrict__ X, const float* __restrict__ Wd,
                               const float* __restrict__ bd, float* __restrict__ out, int B)
{
    int warp = (blockIdx.x * blockDim.x + threadIdx.x) >> 5;
    int lane = threadIdx.x & 31;
    if (warp >= B) return;
    const float4* row = reinterpret_cast<const float4*>(X + (size_t)warp * HID);
    const float4* w = reinterpret_cast<const float4*>(Wd);
    float s = 0.f;
    #pragma unroll
    for (int i = lane; i < HID / 4; i += 32) {
        float4 a = row[i], bw = w[i];
        s += a.x * bw.x + a.y * bw.y + a.z * bw.z + a.w * bw.w;
    }
    #pragma unroll
    for (int o = 16; o > 0; o >>= 1) s += __shfl_down_sync(0xffffffffu, s, o);
    if (lane == 0) out[warp] = s + bd[0];
}

// ---------------------------------------------------------------------------
// Launch
// ---------------------------------------------------------------------------
extern "C" void kernel_launch(void* const* d_in, const int* in_sizes, int n_in,
                              void* d_out, int out_size)
{
    const int*   sizes = (const int*)  d_in[0];
    const float* feat  = (const float*)d_in[1];
    const float* We0   = (const float*)d_in[2];
    const float* be0   = (const float*)d_in[3];
    const float* We1   = (const float*)d_in[4];
    const float* be1   = (const float*)d_in[5];
    const float* Wih   = (const float*)d_in[6];
    const float* bih   = (const float*)d_in[7];
    const float* Whh   = (const float*)d_in[8];
    const float* bhh   = (const float*)d_in[9];
    const float* Wl0   = (const float*)d_in[10];
    const float* bl0   = (const float*)d_in[11];
    const float* Wl1   = (const float*)d_in[12];
    const float* bl1   = (const float*)d_in[13];
    const float* Wd    = (const float*)d_in[14];
    const float* bd    = (const float*)d_in[15];

    const int B  = in_sizes[0];
    const int K0 = in_sizes[2] / HID;
    const int T  = in_sizes[1] / K0;

    __half *feat16, *x1h, *x2h, *xp16, *We0h, *We1h, *Wihp, *Whhp, *h0, *h1;
    float *bsum, *hf, *t0, *t1;
    int *starts;
    cudaGetSymbolAddress((void**)&feat16, g_feat16);
    cudaGetSymbolAddress((void**)&x1h,   g_x1h);
    cudaGetSymbolAddress((void**)&x2h,   g_x2h);
    cudaGetSymbolAddress((void**)&xp16,  g_xp16);
    cudaGetSymbolAddress((void**)&We0h,  g_We0h);
    cudaGetSymbolAddress((void**)&We1h,  g_We1h);
    cudaGetSymbolAddress((void**)&Wihp,  g_Wihp);
    cudaGetSymbolAddress((void**)&Whhp,  g_Whhp);
    cudaGetSymbolAddress((void**)&bsum,  g_bsum);
    cudaGetSymbolAddress((void**)&h0,    g_h0);
    cudaGetSymbolAddress((void**)&h1,    g_h1);
    cudaGetSymbolAddress((void**)&hf,    g_hf);
    cudaGetSymbolAddress((void**)&t0,    g_t0);
    cudaGetSymbolAddress((void**)&t1,    g_t1);
    cudaGetSymbolAddress((void**)&starts, g_starts);

    cudaFuncSetAttribute(lstm_persist, cudaFuncAttributeMaxDynamicSharedMemorySize, LSTM_SMEM);
    cudaFuncSetAttribute(hgemm_nt<true, true>,  cudaFuncAttributeMaxDynamicSharedMemorySize, HG_SMEM);
    cudaFuncSetAttribute(hgemm_nt<false, false>, cudaFuncAttributeMaxDynamicSharedMemorySize, HG_SMEM);

    // launch 1: starts scan
    scan_starts_kernel<<<1, BMAX>>>(sizes, starts, B);

    // launch 2: merged prep (now also zeroes dataflow flags)
    const int nb_feat = (T * K0PAD + 255) / 256;
    const int prep_blocks = nb_feat + 384 + 1024 + 4096 + 4096 + 8 + 16 + 2048;
    prep_kernel<<<prep_blocks, 256>>>(feat, We0, We1, Wih, Whh, bih, bhh, T, K0, nb_feat);

    // launches 3-5: encoder + xproj
    const int mblkT = (T + 127) / 128;
    hgemm_nt<true, true><<<dim3(HID / 128, mblkT), 256, HG_SMEM>>>(feat16, We0h, be0, x1h, T, HID, K0PAD);
    hgemm_nt<true, true><<<dim3(HID / 128, mblkT), 256, HG_SMEM>>>(x1h, We1h, be1, x2h, T, HID, HID);
    hgemm_nt<false, false><<<dim3(GATES / 128, mblkT), 256, HG_SMEM>>>(x2h, Wihp, nullptr, xp16, T, GATES, HID);

    // launch 6: persistent LSTM (dataflow-flag pipelined)
    lstm_persist<<<NCTA, LNT, LSTM_SMEM>>>(Whhp, xp16, bsum, starts, sizes, h0, h1, hf);

    // tail
    gemm_nt_kernel<<<dim3(HID / BN, B / BM), 256>>>(hf, Wl0, bl0, hf, t0, B, HID, HID);
    gemm_nt_kernel<<<dim3(HID / BN, B / BM), 256>>>(t0, Wl1, bl1, t0, t1, B, HID, HID);
    decoder_kernel<<<(B * 32 + 255) / 256, 256>>>(t1, Wd, bd, (float*)d_out, B);
}

// round 14
// speedup vs baseline: 1.0360x; 1.0360x over previous
#include <cuda_runtime.h>
#include <cuda_fp16.h>
#include <math.h>
#include <stdint.h>

// ---------------------------------------------------------------------------
// Problem constants
// ---------------------------------------------------------------------------
#define HID    512
#define GATES  2048
#define MAXLEN 128
#define BMAX   1024
#define TMAX   (BMAX * 127)
#define K0PAD  192
#define NCTA   128         // persistent LSTM grid (16 nblk x 8 mblk)
#define NGRP   8
#define GRPSZ  16

// LSTM chunking
#define CH        64
#define NKT       8
#define AS_STRIDE 72
#define AS_STAGE  (128 * AS_STRIDE)

// front-end GEMM: CTA tile 256x128, warp tile 64x64, 3-stage ring
#define HG2_STRIDE 72
#define HG2_ASTAGE (256 * HG2_STRIDE)           // halves per A stage
#define HG2_BSTAGE (128 * HG2_STRIDE)           // halves per B stage
#define HG2_SMEM   ((3 * HG2_ASTAGE + 3 * HG2_BSTAGE) * 2)   // 165888 bytes

// ---------------------------------------------------------------------------
// Scratch
// ---------------------------------------------------------------------------
__device__ __half g_feat16[(size_t)TMAX * K0PAD];
__device__ __half g_x1h  [(size_t)TMAX * HID];
__device__ __half g_x2h  [(size_t)TMAX * HID];
__device__ __half g_xp16 [(size_t)TMAX * GATES];
__device__ __half g_We0h [HID * K0PAD];
__device__ __half g_We1h [HID * HID];
__device__ __half g_Wihp [GATES * HID];     // gate-interleaved rows
__device__ __half g_Whhp [GATES * HID];     // gate-interleaved rows
__device__ float  g_bsum [GATES];           // gate-interleaved bih+bhh
__device__ __half g_h0   [BMAX * HID];
__device__ __half g_h1   [BMAX * HID];
__device__ float  g_hf   [BMAX * HID];
__device__ float  g_t0   [BMAX * HID];
__device__ float  g_t1   [BMAX * HID];
__device__ int    g_starts[BMAX];
// per-group barrier state on separate 128B lines
__device__ unsigned          g_cnt8[NGRP][32];
__device__ volatile unsigned g_gen8[NGRP][32];

// ---------------------------------------------------------------------------
// Helpers
// ---------------------------------------------------------------------------
__device__ __forceinline__ uint32_t smem_u32(const void* p) {
    return (uint32_t)__cvta_generic_to_shared(p);
}
__device__ __forceinline__ void cp_async16(void* dst, const void* src, bool pred) {
    uint32_t d = smem_u32(dst);
    int sz = pred ? 16 : 0;
    asm volatile("cp.async.cg.shared.global [%0], [%1], 16, %2;\n"
                 :: "r"(d), "l"(src), "r"(sz));
}
__device__ __forceinline__ void cp_commit() { asm volatile("cp.async.commit_group;\n"); }
template<int N> __device__ __forceinline__ void cp_wait() {
    asm volatile("cp.async.wait_group %0;\n" :: "n"(N));
}
__device__ __forceinline__ void ldm_x4(uint32_t addr, uint32_t& r0, uint32_t& r1,
                                       uint32_t& r2, uint32_t& r3) {
    asm volatile("ldmatrix.sync.aligned.m8n8.x4.shared.b16 {%0,%1,%2,%3}, [%4];"
                 : "=r"(r0), "=r"(r1), "=r"(r2), "=r"(r3) : "r"(addr));
}
__device__ __forceinline__ void mma16816(float* c, const uint32_t* a, const uint32_t* b) {
    asm volatile("mma.sync.aligned.m16n8k16.row.col.f32.f16.f16.f32 "
                 "{%0,%1,%2,%3}, {%4,%5,%6,%7}, {%8,%9}, {%0,%1,%2,%3};"
                 : "+f"(c[0]), "+f"(c[1]), "+f"(c[2]), "+f"(c[3])
                 : "r"(a[0]), "r"(a[1]), "r"(a[2]), "r"(a[3]), "r"(b[0]), "r"(b[1]));
}
__device__ __forceinline__ float fast_sigmoid(float x) {
    return __fdividef(1.f, 1.f + __expf(-x));
}
__device__ __forceinline__ float fast_tanh(float x) {
    float xc = fminf(fmaxf(x, -8.f), 8.f);
    float e = __expf(2.f * xc);
    return __fdividef(e - 1.f, e + 1.f);
}

// ---------------------------------------------------------------------------
// setup: scan (launch 1) + merged prep (launch 2)
// ---------------------------------------------------------------------------
__global__ void scan_starts_kernel(const int* __restrict__ sizes, int* __restrict__ starts, int B) {
    __shared__ int s[BMAX];
    int tid = threadIdx.x;
    if (tid < B) s[tid] = sizes[tid];
    __syncthreads();
    if (tid == 0) {
        int acc = 0;
        for (int i = 0; i < B; i++) { starts[i] = acc; acc += s[i]; }
    }
}

__global__ void prep_kernel(const float* __restrict__ feat,
                            const float* __restrict__ We0, const float* __restrict__ We1,
                            const float* __restrict__ Wih, const float* __restrict__ Whh,
                            const float* __restrict__ bih, const float* __restrict__ bhh,
                            int T, int K0, int nb_feat)
{
    int b = blockIdx.x, tid = threadIdx.x;
    if (b < nb_feat) {
        int i = b * 256 + tid;
        if (i < T * K0PAD) {
            int r = i / K0PAD, c = i - r * K0PAD;
            g_feat16[i] = __float2half(c < K0 ? feat[(size_t)r * K0 + c] : 0.f);
        }
        return;
    }
    b -= nb_feat;
    if (b < 384) {
        int i = b * 256 + tid;
        int r = i / K0PAD, c = i - r * K0PAD;
        g_We0h[i] = __float2half(c < K0 ? We0[(size_t)r * K0 + c] : 0.f);
        return;
    }
    b -= 384;
    if (b < 1024) {
        int i = b * 256 + tid;
        g_We1h[i] = __float2half(We1[i]);
        return;
    }
    b -= 1024;
    if (b < 4096) {
        int i = b * 256 + tid;
        int r = i >> 9, c = i & 511;
        int g = r >> 9, hid = r & 511;
        g_Wihp[(size_t)(hid * 4 + g) * HID + c] = __float2half(Wih[i]);
        return;
    }
    b -= 4096;
    if (b < 4096) {
        int i = b * 256 + tid;
        int r = i >> 9, c = i & 511;
        int g = r >> 9, hid = r & 511;
        g_Whhp[(size_t)(hid * 4 + g) * HID + c] = __float2half(Whh[i]);
        return;
    }
    b -= 4096;
    if (b < 8) {
        int o = b * 256 + tid;
        int hid = o >> 2, g = o & 3;
        g_bsum[o] = bih[g * HID + hid] + bhh[g * HID + hid];
        return;
    }
    b -= 8;
    {
        int i = b * 256 + tid;
        g_h0[i] = __float2half(0.f);
    }
}

// ---------------------------------------------------------------------------
// fp16 NT GEMM v2: CTA tile 256x128, warp tile 64x64 (8 warps), 64-col K
// chunks, 3-stage cp.async ring, ONE sync per chunk, 1 CTA/SM.
// Raises smem-fragment reuse to 32.7 FLOP/B (past the 28 FLOP/B LDSM wall).
// ---------------------------------------------------------------------------
template<bool RELU, bool HAS_BIAS>
__global__ __launch_bounds__(256, 1)
void hgemm_nt2(const __half* __restrict__ A, const __half* __restrict__ B,
               const float* __restrict__ bias, __half* __restrict__ Cout,
               int M, int N, int K)
{
    extern __shared__ char smem[];
    __half* As = (__half*)smem;                           // [3][256][72]
    __half* Bs = (__half*)(smem + 3 * HG2_ASTAGE * 2);    // [3][128][72]

    const int m0 = blockIdx.y * 256;
    const int n0 = blockIdx.x * 128;
    const int tid = threadIdx.x;
    const int warp = tid >> 5, lane = tid & 31;
    const int wm = (warp & 3) * 64;
    const int wn = (warp >> 2) * 64;

    float acc[4][8][4];
    #pragma unroll
    for (int i = 0; i < 4; i++)
        #pragma unroll
        for (int j = 0; j < 8; j++)
            #pragma unroll
            for (int q = 0; q < 4; q++) acc[i][j][q] = 0.f;

    const int KT = K >> 6;

    auto load_chunk = [&](int c, int s) {
        const int k0 = c << 6;
        for (int i = tid; i < 2048; i += 256) {
            int r = i >> 3, ch = i & 7;
            int gm = m0 + r;
            bool p = gm < M;
            cp_async16(&As[s * HG2_ASTAGE + r * HG2_STRIDE + ch * 8],
                       A + (size_t)(p ? gm : 0) * K + k0 + ch * 8, p);
        }
        for (int i = tid; i < 1024; i += 256) {
            int r = i >> 3, ch = i & 7;
            cp_async16(&Bs[s * HG2_BSTAGE + r * HG2_STRIDE + ch * 8],
                       B + (size_t)(n0 + r) * K + k0 + ch * 8, true);
        }
        cp_commit();
    };

    load_chunk(0, 0);
    if (KT > 1) load_chunk(1, 1);

    for (int kt = 0; kt < KT; kt++) {
        if (kt + 1 < KT) cp_wait<1>(); else cp_wait<0>();
        __syncthreads();
        if (kt + 2 < KT) load_chunk(kt + 2, (kt + 2) % 3);

        const int stage = kt % 3;
        #pragma unroll
        for (int s = 0; s < 4; s++) {
            uint32_t afrag[4][4];
            #pragma unroll
            for (int mi = 0; mi < 4; mi++) {
                int r = wm + mi * 16 + (lane & 15);
                int c = s * 16 + (lane >> 4) * 8;
                ldm_x4(smem_u32(&As[stage * HG2_ASTAGE + r * HG2_STRIDE + c]),
                       afrag[mi][0], afrag[mi][1], afrag[mi][2], afrag[mi][3]);
            }
            uint32_t bfrag[8][2];
            #pragma unroll
            for (int njp = 0; njp < 4; njp++) {
                int g = lane >> 3;
                int nrow = wn + njp * 16 + (g >> 1) * 8 + (lane & 7);
                int c = s * 16 + (g & 1) * 8;
                uint32_t r0, r1, r2, r3;
                ldm_x4(smem_u32(&Bs[stage * HG2_BSTAGE + nrow * HG2_STRIDE + c]), r0, r1, r2, r3);
                bfrag[njp * 2][0] = r0; bfrag[njp * 2][1] = r1;
                bfrag[njp * 2 + 1][0] = r2; bfrag[njp * 2 + 1][1] = r3;
            }
            #pragma unroll
            for (int mi = 0; mi < 4; mi++)
                #pragma unroll
                for (int ni = 0; ni < 8; ni++)
                    mma16816(acc[mi][ni], afrag[mi], bfrag[ni]);
        }
    }

    const int r_lo = lane >> 2;
    const int cpair = (lane & 3) * 2;
    #pragma unroll
    for (int mi = 0; mi < 4; mi++) {
        #pragma unroll
        for (int hr = 0; hr < 2; hr++) {
            int gr = m0 + wm + mi * 16 + r_lo + hr * 8;
            if (gr >= M) continue;
            #pragma unroll
            for (int ni = 0; ni < 8; ni++) {
                int gc = n0 + wn + ni * 8 + cpair;
                float v0 = acc[mi][ni][hr * 2 + 0];
                float v1 = acc[mi][ni][hr * 2 + 1];
                if (HAS_BIAS) { v0 += bias[gc]; v1 += bias[gc + 1]; }
                if (RELU) { v0 = fmaxf(v0, 0.f); v1 = fmaxf(v1, 0.f); }
                __half2 hv;
                hv.x = __float2half(v0); hv.y = __float2half(v1);
                *reinterpret_cast<__half2*>(Cout + (size_t)gr * N + gc) = hv;
            }
        }
    }
}

// ---------------------------------------------------------------------------
// Persistent LSTM (R12 version: group barrier, 16 warps, fast-math epilogue)
// ---------------------------------------------------------------------------
#define LSTM_SMEM 212480
#define LNT 512

__device__ __forceinline__ void group_sync(int grp) {
    __syncthreads();
    if (threadIdx.x == 0) {
        __threadfence();
        unsigned gen = g_gen8[grp][0];
        if (atomicAdd(&g_cnt8[grp][0], 1) == GRPSZ - 1) {
            g_cnt8[grp][0] = 0;
            __threadfence();
            g_gen8[grp][0] = gen + 1;
        } else {
            while (g_gen8[grp][0] == gen) { }
        }
    }
    __syncthreads();
}

__global__ __launch_bounds__(LNT, 1)
void lstm_persist(const __half* __restrict__ Whp, const __half* __restrict__ xp,
                  const float* __restrict__ bsum,
                  const int* __restrict__ starts, const int* __restrict__ sizes,
                  __half* __restrict__ hbuf0, __half* __restrict__ hbuf1,
                  float* __restrict__ hf)
{
    extern __shared__ char smem[];
    __half* WhS = (__half*)(smem);
    __half* AS  = (__half*)(smem + 133120);
    __half* xpS = (__half*)(smem + 169984);
    float*  bsS = (float*) (smem + 202752);
    int*    stS = (int*)   (smem + 203264);
    int*    szS = (int*)   (smem + 203776);
    __half* hS  = (__half*)(smem + 204288);

    const int tid  = threadIdx.x;
    const int warp = tid >> 5, lane = tid & 31;
    const int nblk = blockIdx.x & 15, mblk = blockIdx.x >> 4;
    const int n0 = nblk * 128, m0 = mblk * 128;
    const int wm = (warp & 3) * 32;
    const int wn = (warp >> 2) * 32;

    for (int i = tid; i < 128 * 64; i += LNT) {
        int r = i >> 6, ch = i & 63;
        cp_async16(&WhS[r * 520 + ch * 8], Whp + (size_t)(n0 + r) * HID + ch * 8, true);
    }
    cp_commit();
    for (int i = tid; i < 128; i += LNT) {
        bsS[i] = bsum[n0 + i];
        stS[i] = starts[m0 + i];
        szS[i] = sizes[m0 + i];
    }
    cp_wait<0>();
    __syncthreads();

    float creg[2][2][4];
    #pragma unroll
    for (int mi = 0; mi < 2; mi++)
        #pragma unroll
        for (int hr = 0; hr < 2; hr++)
            #pragma unroll
            for (int ni = 0; ni < 4; ni++) creg[mi][hr][ni] = 0.f;

    for (int i = tid; i < 2048; i += LNT) {
        int rl = i >> 4, ch = i & 15;
        bool pv = 0 < szS[rl];
        cp_async16(&xpS[rl * 128 + ch * 8], xp + (size_t)stS[rl] * GATES + n0 + ch * 8, pv);
    }
    for (int i = tid; i < 1024; i += LNT) {
        int r = i >> 3, ch = i & 7;
        cp_async16(&AS[r * AS_STRIDE + ch * 8], hbuf0 + (size_t)(m0 + r) * HID + ch * 8, true);
    }
    cp_commit();

    for (int t = 0; t < MAXLEN; t++) {
        const __half* hA = (t & 1) ? hbuf1 : hbuf0;
        __half*       hN = (t & 1) ? hbuf0 : hbuf1;

        float acc[2][4][4];
        #pragma unroll
        for (int mi = 0; mi < 2; mi++)
            #pragma unroll
            for (int ni = 0; ni < 4; ni++)
                #pragma unroll
                for (int q = 0; q < 4; q++) acc[mi][ni][q] = 0.f;

        for (int kt = 0; kt < NKT; kt++) {
            cp_wait<0>();
            __syncthreads();
            if (kt < NKT - 1) {
                const int k0 = (kt + 1) * CH;
                const int stg = (kt + 1) & 1;
                for (int i = tid; i < 1024; i += LNT) {
                    int r = i >> 3, ch = i & 7;
                    cp_async16(&AS[stg * AS_STAGE + r * AS_STRIDE + ch * 8],
                               hA + (size_t)(m0 + r) * HID + k0 + ch * 8, true);
                }
                cp_commit();
            }
            const int stage = kt & 1;
            #pragma unroll
            for (int s = 0; s < 4; s++) {
                const int ks = kt * 4 + s;
                uint32_t afrag[2][4];
                #pragma unroll
                for (int mi = 0; mi < 2; mi++) {
                    int r = wm + mi * 16 + (lane & 15);
                    int c = s * 16 + (lane >> 4) * 8;
                    ldm_x4(smem_u32(&AS[stage * AS_STAGE + r * AS_STRIDE + c]),
                           afrag[mi][0], afrag[mi][1], afrag[mi][2], afrag[mi][3]);
                }
                uint32_t bfrag[4][2];
                #pragma unroll
                for (int njp = 0; njp < 2; njp++) {
                    int g = lane >> 3;
                    int nrow = wn + njp * 16 + (g >> 1) * 8 + (lane & 7);
                    int c = ks * 16 + (g & 1) * 8;
                    uint32_t r0, r1, r2, r3;
                    ldm_x4(smem_u32(&WhS[nrow * 520 + c]), r0, r1, r2, r3);
                    bfrag[njp * 2][0] = r0; bfrag[njp * 2][1] = r1;
                    bfrag[njp * 2 + 1][0] = r2; bfrag[njp * 2 + 1][1] = r3;
                }
                #pragma unroll
                for (int mi = 0; mi < 2; mi++)
                    #pragma unroll
                    for (int ni = 0; ni < 4; ni++)
                        mma16816(acc[mi][ni], afrag[mi], bfrag[ni]);
            }
        }

        const int hlq = (lane & 3) >> 1;
        const int rbase = wm + (lane >> 2);
        #pragma unroll
        for (int mi = 0; mi < 2; mi++) {
            #pragma unroll
            for (int hr = 0; hr < 2; hr++) {
                const int rl = rbase + mi * 16 + hr * 8;
                #pragma unroll
                for (int ni = 0; ni < 4; ni++) {
                    float v0 = acc[mi][ni][hr * 2 + 0];
                    float v1 = acc[mi][ni][hr * 2 + 1];
                    float w0 = __shfl_xor_sync(0xffffffffu, v0, 1);
                    float w1 = __shfl_xor_sync(0xffffffffu, v1, 1);
                    if ((lane & 1) == 0) {
                        const int hl = ((wn + ni * 8) >> 2) + hlq;
                        float gi = v0 + bsS[hl * 4 + 0];
                        float gf = v1 + bsS[hl * 4 + 1];
                        float gg = w0 + bsS[hl * 4 + 2];
                        float go = w1 + bsS[hl * 4 + 3];
                        if (t < szS[rl]) {
                            uint2 xv = *reinterpret_cast<const uint2*>(&xpS[rl * 128 + hl * 4]);
                            __half2 x01 = *reinterpret_cast<__half2*>(&xv.x);
                            __half2 x23 = *reinterpret_cast<__half2*>(&xv.y);
                            gi += __half2float(x01.x);
                            gf += __half2float(x01.y);
                            gg += __half2float(x23.x);
                            go += __half2float(x23.y);
                        }
                        float is = fast_sigmoid(gi);
                        float fs = fast_sigmoid(gf);
                        float gt = fast_tanh(gg);
                        float os = fast_sigmoid(go);
                        float cn = fs * creg[mi][hr][ni] + is * gt;
                        creg[mi][hr][ni] = cn;
                        hS[rl * 32 + hl] = __float2half(os * fast_tanh(cn));
                    }
                }
            }
        }
        __syncthreads();
        for (int i = tid; i < 512; i += LNT) {
            int r = i >> 2, ch = i & 3;
            *reinterpret_cast<uint4*>(hN + (size_t)(m0 + r) * HID + nblk * 32 + ch * 8) =
                *reinterpret_cast<const uint4*>(&hS[r * 32 + ch * 8]);
        }
        if (t == MAXLEN - 1) {
            for (int i = tid; i < 4096; i += LNT) {
                int r = i >> 5, cch = i & 31;
                hf[(size_t)(m0 + r) * HID + nblk * 32 + cch] = __half2float(hS[r * 32 + cch]);
            }
            break;
        }

        for (int i = tid; i < 2048; i += LNT) {
            int rl = i >> 4, ch = i & 15;
            bool pv = (t + 1) < szS[rl];
            cp_async16(&xpS[rl * 128 + ch * 8],
                       xp + (size_t)(stS[rl] + t + 1) * GATES + n0 + ch * 8, pv);
        }
        cp_commit();

        group_sync(mblk);

        for (int i = tid; i < 1024; i += LNT) {
            int r = i >> 3, ch = i & 7;
            cp_async16(&AS[r * AS_STRIDE + ch * 8], hN + (size_t)(m0 + r) * HID + ch * 8, true);
        }
        cp_commit();
    }
}

// ---------------------------------------------------------------------------
// fp32 tail GEMM + decoder
// ---------------------------------------------------------------------------
#define BM 64
#define BN 64
#define BK 16
__global__ __launch_bounds__(256) void gemm_nt_kernel(
    const float* __restrict__ A, const float* __restrict__ B,
    const float* __restrict__ bias, const float* __restrict__ R,
    float* __restrict__ C, int M, int N, int K)
{
    __shared__ float As[BK][BM];
    __shared__ float Bs[BK][BN];
    const int m0 = blockIdx.y * BM;
    const int n0 = blockIdx.x * BN;
    const int tid = threadIdx.x;
    const int tx = tid & 15, ty = tid >> 4;
    const int lrow = tid >> 2, lkq = (tid & 3) * 4;
    float acc[4][4] = {};
    for (int k0 = 0; k0 < K; k0 += BK) {
        {
            int gm = m0 + lrow;
            float4 v = make_float4(0.f, 0.f, 0.f, 0.f);
            if (gm < M) v = *reinterpret_cast<const float4*>(A + (size_t)gm * K + k0 + lkq);
            As[lkq + 0][lrow] = v.x; As[lkq + 1][lrow] = v.y;
            As[lkq + 2][lrow] = v.z; As[lkq + 3][lrow] = v.w;
        }
        {
            float4 v = *reinterpret_cast<const float4*>(B + (size_t)(n0 + lrow) * K + k0 + lkq);
            Bs[lkq + 0][lrow] = v.x; Bs[lkq + 1][lrow] = v.y;
            Bs[lkq + 2][lrow] = v.z; Bs[lkq + 3][lrow] = v.w;
        }
        __syncthreads();
        #pragma unroll
        for (int k = 0; k < BK; k++) {
            float4 a = *reinterpret_cast<const float4*>(&As[k][ty * 4]);
            float4 b = *reinterpret_cast<const float4*>(&Bs[k][tx * 4]);
            acc[0][0] += a.x * b.x; acc[0][1] += a.x * b.y; acc[0][2] += a.x * b.z; acc[0][3] += a.x * b.w;
            acc[1][0] += a.y * b.x; acc[1][1] += a.y * b.y; acc[1][2] += a.y * b.z; acc[1][3] += a.y * b.w;
            acc[2][0] += a.z * b.x; acc[2][1] += a.z * b.y; acc[2][2] += a.z * b.z; acc[2][3] += a.z * b.w;
            acc[3][0] += a.w * b.x; acc[3][1] += a.w * b.y; acc[3][2] += a.w * b.z; acc[3][3] += a.w * b.w;
        }
        __syncthreads();
    }
    #pragma unroll
    for (int i = 0; i < 4; i++) {
        int gm = m0 + ty * 4 + i;
        if (gm >= M) continue;
        #pragma unroll
        for (int j = 0; j < 4; j++) {
            int gn = n0 + tx * 4 + j;
            float v = acc[i][j] + bias[gn];
            v = fmaxf(v, 0.f);
            v += R[(size_t)gm * N + gn];
            C[(size_t)gm * N + gn] = v;
        }
    }
}

__global__ void decoder_kernel(const float* __restrict__ X, const float* __restrict__ Wd,
                               const float* __restrict__ bd, float* __restrict__ out, int B)
{
    int warp = (blockIdx.x * blockDim.x + threadIdx.x) >> 5;
    int lane = threadIdx.x & 31;
    if (warp >= B) return;
    const float4* row = reinterpret_cast<const float4*>(X + (size_t)warp * HID);
    const float4* w = reinterpret_cast<const float4*>(Wd);
    float s = 0.f;
    #pragma unroll
    for (int i = lane; i < HID / 4; i += 32) {
        float4 a = row[i], bw = w[i];
        s += a.x * bw.x + a.y * bw.y + a.z * bw.z + a.w * bw.w;
    }
    #pragma unroll
    for (int o = 16; o > 0; o >>= 1) s += __shfl_down_sync(0xffffffffu, s, o);
    if (lane == 0) out[warp] = s + bd[0];
}

// ---------------------------------------------------------------------------
// Launch
// ---------------------------------------------------------------------------
extern "C" void kernel_launch(void* const* d_in, const int* in_sizes, int n_in,
                              void* d_out, int out_size)
{
    const int*   sizes = (const int*)  d_in[0];
    const float* feat  = (const float*)d_in[1];
    const float* We0   = (const float*)d_in[2];
    const float* be0   = (const float*)d_in[3];
    const float* We1   = (const float*)d_in[4];
    const float* be1   = (const float*)d_in[5];
    const float* Wih   = (const float*)d_in[6];
    const float* bih   = (const float*)d_in[7];
    const float* Whh   = (const float*)d_in[8];
    const float* bhh   = (const float*)d_in[9];
    const float* Wl0   = (const float*)d_in[10];
    const float* bl0   = (const float*)d_in[11];
    const float* Wl1   = (const float*)d_in[12];
    const float* bl1   = (const float*)d_in[13];
    const float* Wd    = (const float*)d_in[14];
    const float* bd    = (const float*)d_in[15];

    const int B  = in_sizes[0];
    const int K0 = in_sizes[2] / HID;
    const int T  = in_sizes[1] / K0;

    __half *feat16, *x1h, *x2h, *xp16, *We0h, *We1h, *Wihp, *Whhp, *h0, *h1;
    float *bsum, *hf, *t0, *t1;
    int *starts;
    cudaGetSymbolAddress((void**)&feat16, g_feat16);
    cudaGetSymbolAddress((void**)&x1h,   g_x1h);
    cudaGetSymbolAddress((void**)&x2h,   g_x2h);
    cudaGetSymbolAddress((void**)&xp16,  g_xp16);
    cudaGetSymbolAddress((void**)&We0h,  g_We0h);
    cudaGetSymbolAddress((void**)&We1h,  g_We1h);
    cudaGetSymbolAddress((void**)&Wihp,  g_Wihp);
    cudaGetSymbolAddress((void**)&Whhp,  g_Whhp);
    cudaGetSymbolAddress((void**)&bsum,  g_bsum);
    cudaGetSymbolAddress((void**)&h0,    g_h0);
    cudaGetSymbolAddress((void**)&h1,    g_h1);
    cudaGetSymbolAddress((void**)&hf,    g_hf);
    cudaGetSymbolAddress((void**)&t0,    g_t0);
    cudaGetSymbolAddress((void**)&t1,    g_t1);
    cudaGetSymbolAddress((void**)&starts, g_starts);

    cudaFuncSetAttribute(lstm_persist, cudaFuncAttributeMaxDynamicSharedMemorySize, LSTM_SMEM);
    cudaFuncSetAttribute(hgemm_nt2<true, true>,  cudaFuncAttributeMaxDynamicSharedMemorySize, HG2_SMEM);
    cudaFuncSetAttribute(hgemm_nt2<false, false>, cudaFuncAttributeMaxDynamicSharedMemorySize, HG2_SMEM);

    // launch 1: starts scan
    scan_starts_kernel<<<1, BMAX>>>(sizes, starts, B);

    // launch 2: merged prep
    const int nb_feat = (T * K0PAD + 255) / 256;
    const int prep_blocks = nb_feat + 384 + 1024 + 4096 + 4096 + 8 + 2048;
    prep_kernel<<<prep_blocks, 256>>>(feat, We0, We1, Wih, Whh, bih, bhh, T, K0, nb_feat);

    // launches 3-5: encoder + xproj (256x128 tiles, 64x64 warp tiles)
    const int mblkT = (T + 255) / 256;
    hgemm_nt2<true, true><<<dim3(HID / 128, mblkT), 256, HG2_SMEM>>>(feat16, We0h, be0, x1h, T, HID, K0PAD);
    hgemm_nt2<true, true><<<dim3(HID / 128, mblkT), 256, HG2_SMEM>>>(x1h, We1h, be1, x2h, T, HID, HID);
    hgemm_nt2<false, false><<<dim3(GATES / 128, mblkT), 256, HG2_SMEM>>>(x2h, Wihp, nullptr, xp16, T, GATES, HID);

    // launch 6: persistent LSTM (R12 group-barrier version)
    lstm_persist<<<NCTA, LNT, LSTM_SMEM>>>(Whhp, xp16, bsum, starts, sizes, h0, h1, hf);

    // tail
    gemm_nt_kernel<<<dim3(HID / BN, B / BM), 256>>>(hf, Wl0, bl0, hf, t0, B, HID, HID);
    gemm_nt_kernel<<<dim3(HID / BN, B / BM), 256>>>(t0, Wl1, bl1, t0, t1, B, HID, HID);
    decoder_kernel<<<(B * 32 + 255) / 256, 256>>>(t1, Wd, bd, (float*)d_out, B);
}

// round 15
// speedup vs baseline: 1.1824x; 1.1413x over previous
#include <cuda_runtime.h>
#include <cuda_fp16.h>
#include <math.h>
#include <stdint.h>

// ---------------------------------------------------------------------------
// Problem constants
// ---------------------------------------------------------------------------
#define HID    512
#define GATES  2048
#define MAXLEN 128
#define BMAX   1024
#define TMAX   (BMAX * 127)
#define K0PAD  192
#define NCTA   128         // persistent LSTM grid (16 nblk x 8 mblk)
#define NGRP   8
#define GRPSZ  16

// LSTM chunking
#define CH        64
#define NKT       8
#define AS_STRIDE 72
#define AS_STAGE  (128 * AS_STRIDE)

// hgemm: 64-col K chunks, 3 stages (R12 config)
#define HG_STRIDE 72
#define HG_STAGE  (128 * HG_STRIDE)
#define HG_SMEM   (6 * HG_STAGE * 2)

// ---------------------------------------------------------------------------
// Scratch
// ---------------------------------------------------------------------------
__device__ __half g_feat16[(size_t)TMAX * K0PAD];
__device__ __half g_x1h  [(size_t)TMAX * HID];
__device__ __half g_x2h  [(size_t)TMAX * HID];
__device__ __half g_xp16 [(size_t)TMAX * GATES];
__device__ __half g_We0h [HID * K0PAD];
__device__ __half g_We1h [HID * HID];
__device__ __half g_Wihp [GATES * HID];     // gate-interleaved rows
__device__ __half g_Whhp [GATES * HID];     // gate-interleaved rows
__device__ float  g_bsum [GATES];           // gate-interleaved bih+bhh
__device__ __half g_h0   [BMAX * HID];
__device__ __half g_h1   [BMAX * HID];
__device__ float  g_hf   [BMAX * HID];
__device__ float  g_t0   [BMAX * HID];
__device__ float  g_t1   [BMAX * HID];
__device__ int    g_starts[BMAX];
// per-group barrier state on separate 128B lines
__device__ unsigned          g_cnt8[NGRP][32];
__device__ volatile unsigned g_gen8[NGRP][32];

// ---------------------------------------------------------------------------
// Helpers
// ---------------------------------------------------------------------------
__device__ __forceinline__ uint32_t smem_u32(const void* p) {
    return (uint32_t)__cvta_generic_to_shared(p);
}
__device__ __forceinline__ void cp_async16(void* dst, const void* src, bool pred) {
    uint32_t d = smem_u32(dst);
    int sz = pred ? 16 : 0;
    asm volatile("cp.async.cg.shared.global [%0], [%1], 16, %2;\n"
                 :: "r"(d), "l"(src), "r"(sz));
}
__device__ __forceinline__ void cp_commit() { asm volatile("cp.async.commit_group;\n"); }
template<int N> __device__ __forceinline__ void cp_wait() {
    asm volatile("cp.async.wait_group %0;\n" :: "n"(N));
}
__device__ __forceinline__ void ldm_x4(uint32_t addr, uint32_t& r0, uint32_t& r1,
                                       uint32_t& r2, uint32_t& r3) {
    asm volatile("ldmatrix.sync.aligned.m8n8.x4.shared.b16 {%0,%1,%2,%3}, [%4];"
                 : "=r"(r0), "=r"(r1), "=r"(r2), "=r"(r3) : "r"(addr));
}
__device__ __forceinline__ void mma16816(float* c, const uint32_t* a, const uint32_t* b) {
    asm volatile("mma.sync.aligned.m16n8k16.row.col.f32.f16.f16.f32 "
                 "{%0,%1,%2,%3}, {%4,%5,%6,%7}, {%8,%9}, {%0,%1,%2,%3};"
                 : "+f"(c[0]), "+f"(c[1]), "+f"(c[2]), "+f"(c[3])
                 : "r"(a[0]), "r"(a[1]), "r"(a[2]), "r"(a[3]), "r"(b[0]), "r"(b[1]));
}
__device__ __forceinline__ float fast_sigmoid(float x) {
    return __fdividef(1.f, 1.f + __expf(-x));
}
__device__ __forceinline__ float fast_tanh(float x) {
    float xc = fminf(fmaxf(x, -8.f), 8.f);
    float e = __expf(2.f * xc);
    return __fdividef(e - 1.f, e + 1.f);
}

// ---------------------------------------------------------------------------
// setup: scan (launch 1) + merged prep (launch 2)
// ---------------------------------------------------------------------------
__global__ void scan_starts_kernel(const int* __restrict__ sizes, int* __restrict__ starts, int B) {
    __shared__ int s[BMAX];
    int tid = threadIdx.x;
    if (tid < B) s[tid] = sizes[tid];
    __syncthreads();
    if (tid == 0) {
        int acc = 0;
        for (int i = 0; i < B; i++) { starts[i] = acc; acc += s[i]; }
    }
}

__global__ void prep_kernel(const float* __restrict__ feat,
                            const float* __restrict__ We0, const float* __restrict__ We1,
                            const float* __restrict__ Wih, const float* __restrict__ Whh,
                            const float* __restrict__ bih, const float* __restrict__ bhh,
                            int T, int K0, int nb_feat)
{
    int b = blockIdx.x, tid = threadIdx.x;
    if (b < nb_feat) {
        int i = b * 256 + tid;
        if (i < T * K0PAD) {
            int r = i / K0PAD, c = i - r * K0PAD;
            g_feat16[i] = __float2half(c < K0 ? feat[(size_t)r * K0 + c] : 0.f);
        }
        return;
    }
    b -= nb_feat;
    if (b < 384) {
        int i = b * 256 + tid;
        int r = i / K0PAD, c = i - r * K0PAD;
        g_We0h[i] = __float2half(c < K0 ? We0[(size_t)r * K0 + c] : 0.f);
        return;
    }
    b -= 384;
    if (b < 1024) {
        int i = b * 256 + tid;
        g_We1h[i] = __float2half(We1[i]);
        return;
    }
    b -= 1024;
    if (b < 4096) {
        int i = b * 256 + tid;
        int r = i >> 9, c = i & 511;
        int g = r >> 9, hid = r & 511;
        g_Wihp[(size_t)(hid * 4 + g) * HID + c] = __float2half(Wih[i]);
        return;
    }
    b -= 4096;
    if (b < 4096) {
        int i = b * 256 + tid;
        int r = i >> 9, c = i & 511;
        int g = r >> 9, hid = r & 511;
        g_Whhp[(size_t)(hid * 4 + g) * HID + c] = __float2half(Whh[i]);
        return;
    }
    b -= 4096;
    if (b < 8) {
        int o = b * 256 + tid;
        int hid = o >> 2, g = o & 3;
        g_bsum[o] = bih[g * HID + hid] + bhh[g * HID + hid];
        return;
    }
    b -= 8;
    {
        int i = b * 256 + tid;
        g_h0[i] = __float2half(0.f);
    }
}

// ---------------------------------------------------------------------------
// fp16 NT GEMM (encoder / xproj): 64-col K chunks, ONE sync per chunk,
// 3-stage cp.async ring, 2 CTAs/SM.  (R12 version — best measured.)
// ---------------------------------------------------------------------------
template<bool RELU, bool HAS_BIAS>
__global__ __launch_bounds__(256, 2)
void hgemm_nt(const __half* __restrict__ A, const __half* __restrict__ B,
              const float* __restrict__ bias, __half* __restrict__ Cout,
              int M, int N, int K)
{
    extern __shared__ char smem[];
    __half* As = (__half*)smem;                       // [3][128][72]
    __half* Bs = (__half*)(smem + 3 * HG_STAGE * 2);  // [3][128][72]

    const int m0 = blockIdx.y * 128;
    const int n0 = blockIdx.x * 128;
    const int tid = threadIdx.x;
    const int warp = tid >> 5, lane = tid & 31;
    const int wm = (warp & 3) * 32;
    const int wn = (warp >> 2) * 64;

    float acc[2][8][4];
    #pragma unroll
    for (int i = 0; i < 2; i++)
        #pragma unroll
        for (int j = 0; j < 8; j++)
            #pragma unroll
            for (int q = 0; q < 4; q++) acc[i][j][q] = 0.f;

    const int KT = K >> 6;

    auto load_chunk = [&](int c, int s) {
        const int k0 = c << 6;
        for (int i = tid; i < 1024; i += 256) {
            int r = i >> 3, ch = i & 7;
            int gm = m0 + r;
            bool p = gm < M;
            cp_async16(&As[s * HG_STAGE + r * HG_STRIDE + ch * 8],
                       A + (size_t)(p ? gm : 0) * K + k0 + ch * 8, p);
        }
        for (int i = tid; i < 1024; i += 256) {
            int r = i >> 3, ch = i & 7;
            cp_async16(&Bs[s * HG_STAGE + r * HG_STRIDE + ch * 8],
                       B + (size_t)(n0 + r) * K + k0 + ch * 8, true);
        }
        cp_commit();
    };

    load_chunk(0, 0);
    if (KT > 1) load_chunk(1, 1);

    for (int kt = 0; kt < KT; kt++) {
        if (kt + 1 < KT) cp_wait<1>(); else cp_wait<0>();
        __syncthreads();
        if (kt + 2 < KT) load_chunk(kt + 2, (kt + 2) % 3);

        const int stage = kt % 3;
        #pragma unroll
        for (int s = 0; s < 4; s++) {
            uint32_t afrag[2][4];
            #pragma unroll
            for (int mi = 0; mi < 2; mi++) {
                int r = wm + mi * 16 + (lane & 15);
                int c = s * 16 + (lane >> 4) * 8;
                ldm_x4(smem_u32(&As[stage * HG_STAGE + r * HG_STRIDE + c]),
                       afrag[mi][0], afrag[mi][1], afrag[mi][2], afrag[mi][3]);
            }
            uint32_t bfrag[8][2];
            #pragma unroll
            for (int njp = 0; njp < 4; njp++) {
                int g = lane >> 3;
                int nrow = wn + njp * 16 + (g >> 1) * 8 + (lane & 7);
                int c = s * 16 + (g & 1) * 8;
                uint32_t r0, r1, r2, r3;
                ldm_x4(smem_u32(&Bs[stage * HG_STAGE + nrow * HG_STRIDE + c]), r0, r1, r2, r3);
                bfrag[njp * 2][0] = r0; bfrag[njp * 2][1] = r1;
                bfrag[njp * 2 + 1][0] = r2; bfrag[njp * 2 + 1][1] = r3;
            }
            #pragma unroll
            for (int mi = 0; mi < 2; mi++)
                #pragma unroll
                for (int ni = 0; ni < 8; ni++)
                    mma16816(acc[mi][ni], afrag[mi], bfrag[ni]);
        }
    }

    const int r_lo = lane >> 2;
    const int cpair = (lane & 3) * 2;
    #pragma unroll
    for (int mi = 0; mi < 2; mi++) {
        #pragma unroll
        for (int hr = 0; hr < 2; hr++) {
            int gr = m0 + wm + mi * 16 + r_lo + hr * 8;
            if (gr >= M) continue;
            #pragma unroll
            for (int ni = 0; ni < 8; ni++) {
                int gc = n0 + wn + ni * 8 + cpair;
                float v0 = acc[mi][ni][hr * 2 + 0];
                float v1 = acc[mi][ni][hr * 2 + 1];
                if (HAS_BIAS) { v0 += bias[gc]; v1 += bias[gc + 1]; }
                if (RELU) { v0 = fmaxf(v0, 0.f); v1 = fmaxf(v1, 0.f); }
                __half2 hv;
                hv.x = __float2half(v0); hv.y = __float2half(v1);
                *reinterpret_cast<__half2*>(Cout + (size_t)gr * N + gc) = hv;
            }
        }
    }
}

// ---------------------------------------------------------------------------
// Persistent LSTM: 512 threads (16 warps, 32x32 warp tiles), group barrier,
// PAIR-BALANCED fast-math epilogue: even lane owns cells ni2 (0,1), odd lane
// owns cells ni2+2 (2,3); one parity-selected shfl exchange per pair so all
// 32 lanes compute full cell updates in the same instructions.
// ---------------------------------------------------------------------------
#define LSTM_SMEM 212480
#define LNT 512

__device__ __forceinline__ void group_sync(int grp) {
    __syncthreads();
    if (threadIdx.x == 0) {
        __threadfence();
        unsigned gen = g_gen8[grp][0];
        if (atomicAdd(&g_cnt8[grp][0], 1) == GRPSZ - 1) {
            g_cnt8[grp][0] = 0;
            __threadfence();
            g_gen8[grp][0] = gen + 1;
        } else {
            while (g_gen8[grp][0] == gen) { }
        }
    }
    __syncthreads();
}

__global__ __launch_bounds__(LNT, 1)
void lstm_persist(const __half* __restrict__ Whp, const __half* __restrict__ xp,
                  const float* __restrict__ bsum,
                  const int* __restrict__ starts, const int* __restrict__ sizes,
                  __half* __restrict__ hbuf0, __half* __restrict__ hbuf1,
                  float* __restrict__ hf)
{
    extern __shared__ char smem[];
    __half* WhS = (__half*)(smem);
    __half* AS  = (__half*)(smem + 133120);
    __half* xpS = (__half*)(smem + 169984);
    float*  bsS = (float*) (smem + 202752);
    int*    stS = (int*)   (smem + 203264);
    int*    szS = (int*)   (smem + 203776);
    __half* hS  = (__half*)(smem + 204288);

    const int tid  = threadIdx.x;
    const int warp = tid >> 5, lane = tid & 31;
    const int nblk = blockIdx.x & 15, mblk = blockIdx.x >> 4;
    const int n0 = nblk * 128, m0 = mblk * 128;
    const int wm = (warp & 3) * 32;
    const int wn = (warp >> 2) * 32;

    for (int i = tid; i < 128 * 64; i += LNT) {
        int r = i >> 6, ch = i & 63;
        cp_async16(&WhS[r * 520 + ch * 8], Whp + (size_t)(n0 + r) * HID + ch * 8, true);
    }
    cp_commit();
    for (int i = tid; i < 128; i += LNT) {
        bsS[i] = bsum[n0 + i];
        stS[i] = starts[m0 + i];
        szS[i] = sizes[m0 + i];
    }
    cp_wait<0>();
    __syncthreads();

    // each lane owns 8 cells: [mi][hr][ni2], even lanes cells ni2 / odd ni2+2
    float creg[2][2][2];
    #pragma unroll
    for (int mi = 0; mi < 2; mi++)
        #pragma unroll
        for (int hr = 0; hr < 2; hr++)
            #pragma unroll
            for (int q = 0; q < 2; q++) creg[mi][hr][q] = 0.f;

    for (int i = tid; i < 2048; i += LNT) {
        int rl = i >> 4, ch = i & 15;
        bool pv = 0 < szS[rl];
        cp_async16(&xpS[rl * 128 + ch * 8], xp + (size_t)stS[rl] * GATES + n0 + ch * 8, pv);
    }
    for (int i = tid; i < 1024; i += LNT) {
        int r = i >> 3, ch = i & 7;
        cp_async16(&AS[r * AS_STRIDE + ch * 8], hbuf0 + (size_t)(m0 + r) * HID + ch * 8, true);
    }
    cp_commit();

    const int  hlq  = (lane & 3) >> 1;
    const int  rbase = wm + (lane >> 2);
    const bool oddl = (lane & 1) != 0;
    const int  hbase = wn >> 2;

    for (int t = 0; t < MAXLEN; t++) {
        const __half* hA = (t & 1) ? hbuf1 : hbuf0;
        __half*       hN = (t & 1) ? hbuf0 : hbuf1;

        float acc[2][4][4];
        #pragma unroll
        for (int mi = 0; mi < 2; mi++)
            #pragma unroll
            for (int ni = 0; ni < 4; ni++)
                #pragma unroll
                for (int q = 0; q < 4; q++) acc[mi][ni][q] = 0.f;

        for (int kt = 0; kt < NKT; kt++) {
            cp_wait<0>();
            __syncthreads();
            if (kt < NKT - 1) {
                const int k0 = (kt + 1) * CH;
                const int stg = (kt + 1) & 1;
                for (int i = tid; i < 1024; i += LNT) {
                    int r = i >> 3, ch = i & 7;
                    cp_async16(&AS[stg * AS_STAGE + r * AS_STRIDE + ch * 8],
                               hA + (size_t)(m0 + r) * HID + k0 + ch * 8, true);
                }
                cp_commit();
            }
            const int stage = kt & 1;
            #pragma unroll
            for (int s = 0; s < 4; s++) {
                const int ks = kt * 4 + s;
                uint32_t afrag[2][4];
                #pragma unroll
                for (int mi = 0; mi < 2; mi++) {
                    int r = wm + mi * 16 + (lane & 15);
                    int c = s * 16 + (lane >> 4) * 8;
                    ldm_x4(smem_u32(&AS[stage * AS_STAGE + r * AS_STRIDE + c]),
                           afrag[mi][0], afrag[mi][1], afrag[mi][2], afrag[mi][3]);
                }
                uint32_t bfrag[4][2];
                #pragma unroll
                for (int njp = 0; njp < 2; njp++) {
                    int g = lane >> 3;
                    int nrow = wn + njp * 16 + (g >> 1) * 8 + (lane & 7);
                    int c = ks * 16 + (g & 1) * 8;
                    uint32_t r0, r1, r2, r3;
                    ldm_x4(smem_u32(&WhS[nrow * 520 + c]), r0, r1, r2, r3);
                    bfrag[njp * 2][0] = r0; bfrag[njp * 2][1] = r1;
                    bfrag[njp * 2 + 1][0] = r2; bfrag[njp * 2 + 1][1] = r3;
                }
                #pragma unroll
                for (int mi = 0; mi < 2; mi++)
                    #pragma unroll
                    for (int ni = 0; ni < 4; ni++)
                        mma16816(acc[mi][ni], afrag[mi], bfrag[ni]);
            }
        }

        // ---- pair-balanced fused LSTM epilogue ----
        #pragma unroll
        for (int mi = 0; mi < 2; mi++) {
            #pragma unroll
            for (int hr = 0; hr < 2; hr++) {
                const int rl = rbase + mi * 16 + hr * 8;
                #pragma unroll
                for (int ni2 = 0; ni2 < 2; ni2++) {
                    // cells: even lane -> ni2, odd lane -> ni2+2
                    float va0 = acc[mi][ni2][hr * 2 + 0];
                    float va1 = acc[mi][ni2][hr * 2 + 1];
                    float vb0 = acc[mi][ni2 + 2][hr * 2 + 0];
                    float vb1 = acc[mi][ni2 + 2][hr * 2 + 1];
                    // send the half the partner needs
                    float s0 = oddl ? va0 : vb0;
                    float s1 = oddl ? va1 : vb1;
                    float r0 = __shfl_xor_sync(0xffffffffu, s0, 1);
                    float r1 = __shfl_xor_sync(0xffffffffu, s1, 1);
                    // even lane: i,f = own va; g,o = received. odd: i,f = received; g,o = own vb.
                    float gi = oddl ? r0 : va0;
                    float gf = oddl ? r1 : va1;
                    float gg = oddl ? vb0 : r0;
                    float go = oddl ? vb1 : r1;
                    const int myni = oddl ? (ni2 + 2) : ni2;
                    const int hl = hbase + myni * 2 + hlq;
                    gi += bsS[hl * 4 + 0];
                    gf += bsS[hl * 4 + 1];
                    gg += bsS[hl * 4 + 2];
                    go += bsS[hl * 4 + 3];
                    if (t < szS[rl]) {
                        uint2 xv = *reinterpret_cast<const uint2*>(&xpS[rl * 128 + hl * 4]);
                        __half2 x01 = *reinterpret_cast<__half2*>(&xv.x);
                        __half2 x23 = *reinterpret_cast<__half2*>(&xv.y);
                        gi += __half2float(x01.x);
                        gf += __half2float(x01.y);
                        gg += __half2float(x23.x);
                        go += __half2float(x23.y);
                    }
                    float is = fast_sigmoid(gi);
                    float fs = fast_sigmoid(gf);
                    float gt = fast_tanh(gg);
                    float os = fast_sigmoid(go);
                    float cn = fs * creg[mi][hr][ni2] + is * gt;
                    creg[mi][hr][ni2] = cn;
                    hS[rl * 32 + hl] = __float2half(os * fast_tanh(cn));
                }
            }
        }
        __syncthreads();
        for (int i = tid; i < 512; i += LNT) {
            int r = i >> 2, ch = i & 3;
            *reinterpret_cast<uint4*>(hN + (size_t)(m0 + r) * HID + nblk * 32 + ch * 8) =
                *reinterpret_cast<const uint4*>(&hS[r * 32 + ch * 8]);
        }
        if (t == MAXLEN - 1) {
            for (int i = tid; i < 4096; i += LNT) {
                int r = i >> 5, cch = i & 31;
                hf[(size_t)(m0 + r) * HID + nblk * 32 + cch] = __half2float(hS[r * 32 + cch]);
            }
            break;
        }

        for (int i = tid; i < 2048; i += LNT) {
            int rl = i >> 4, ch = i & 15;
            bool pv = (t + 1) < szS[rl];
            cp_async16(&xpS[rl * 128 + ch * 8],
                       xp + (size_t)(stS[rl] + t + 1) * GATES + n0 + ch * 8, pv);
        }
        cp_commit();

        group_sync(mblk);

        for (int i = tid; i < 1024; i += LNT) {
            int r = i >> 3, ch = i & 7;
            cp_async16(&AS[r * AS_STRIDE + ch * 8], hN + (size_t)(m0 + r) * HID + ch * 8, true);
        }
        cp_commit();
    }
}

// ---------------------------------------------------------------------------
// fp32 tail GEMM + decoder
// ---------------------------------------------------------------------------
#define BM 64
#define BN 64
#define BK 16
__global__ __launch_bounds__(256) void gemm_nt_kernel(
    const float* __restrict__ A, const float* __restrict__ B,
    const float* __restrict__ bias, const float* __restrict__ R,
    float* __restrict__ C, int M, int N, int K)
{
    __shared__ float As[BK][BM];
    __shared__ float Bs[BK][BN];
    const int m0 = blockIdx.y * BM;
    const int n0 = blockIdx.x * BN;
    const int tid = threadIdx.x;
    const int tx = tid & 15, ty = tid >> 4;
    const int lrow = tid >> 2, lkq = (tid & 3) * 4;
    float acc[4][4] = {};
    for (int k0 = 0; k0 < K; k0 += BK) {
        {
            int gm = m0 + lrow;
            float4 v = make_float4(0.f, 0.f, 0.f, 0.f);
            if (gm < M) v = *reinterpret_cast<const float4*>(A + (size_t)gm * K + k0 + lkq);
            As[lkq + 0][lrow] = v.x; As[lkq + 1][lrow] = v.y;
            As[lkq + 2][lrow] = v.z; As[lkq + 3][lrow] = v.w;
        }
        {
            float4 v = *reinterpret_cast<const float4*>(B + (size_t)(n0 + lrow) * K + k0 + lkq);
            Bs[lkq + 0][lrow] = v.x; Bs[lkq + 1][lrow] = v.y;
            Bs[lkq + 2][lrow] = v.z; Bs[lkq + 3][lrow] = v.w;
        }
        __syncthreads();
        #pragma unroll
        for (int k = 0; k < BK; k++) {
            float4 a = *reinterpret_cast<const float4*>(&As[k][ty * 4]);
            float4 b = *reinterpret_cast<const float4*>(&Bs[k][tx * 4]);
            acc[0][0] += a.x * b.x; acc[0][1] += a.x * b.y; acc[0][2] += a.x * b.z; acc[0][3] += a.x * b.w;
            acc[1][0] += a.y * b.x; acc[1][1] += a.y * b.y; acc[1][2] += a.y * b.z; acc[1][3] += a.y * b.w;
            acc[2][0] += a.z * b.x; acc[2][1] += a.z * b.y; acc[2][2] += a.z * b.z; acc[2][3] += a.z * b.w;
            acc[3][0] += a.w * b.x; acc[3][1] += a.w * b.y; acc[3][2] += a.w * b.z; acc[3][3] += a.w * b.w;
        }
        __syncthreads();
    }
    #pragma unroll
    for (int i = 0; i < 4; i++) {
        int gm = m0 + ty * 4 + i;
        if (gm >= M) continue;
        #pragma unroll
        for (int j = 0; j < 4; j++) {
            int gn = n0 + tx * 4 + j;
            float v = acc[i][j] + bias[gn];
            v = fmaxf(v, 0.f);
            v += R[(size_t)gm * N + gn];
            C[(size_t)gm * N + gn] = v;
        }
    }
}

__global__ void decoder_kernel(const float* __restrict__ X, const float* __restrict__ Wd,
                               const float* __restrict__ bd, float* __restrict__ out, int B)
{
    int warp = (blockIdx.x * blockDim.x + threadIdx.x) >> 5;
    int lane = threadIdx.x & 31;
    if (warp >= B) return;
    const float4* row = reinterpret_cast<const float4*>(X + (size_t)warp * HID);
    const float4* w = reinterpret_cast<const float4*>(Wd);
    float s = 0.f;
    #pragma unroll
    for (int i = lane; i < HID / 4; i += 32) {
        float4 a = row[i], bw = w[i];
        s += a.x * bw.x + a.y * bw.y + a.z * bw.z + a.w * bw.w;
    }
    #pragma unroll
    for (int o = 16; o > 0; o >>= 1) s += __shfl_down_sync(0xffffffffu, s, o);
    if (lane == 0) out[warp] = s + bd[0];
}

// ---------------------------------------------------------------------------
// Launch
// ---------------------------------------------------------------------------
extern "C" void kernel_launch(void* const* d_in, const int* in_sizes, int n_in,
                              void* d_out, int out_size)
{
    const int*   sizes = (const int*)  d_in[0];
    const float* feat  = (const float*)d_in[1];
    const float* We0   = (const float*)d_in[2];
    const float* be0   = (const float*)d_in[3];
    const float* We1   = (const float*)d_in[4];
    const float* be1   = (const float*)d_in[5];
    const float* Wih   = (const float*)d_in[6];
    const float* bih   = (const float*)d_in[7];
    const float* Whh   = (const float*)d_in[8];
    const float* bhh   = (const float*)d_in[9];
    const float* Wl0   = (const float*)d_in[10];
    const float* bl0   = (const float*)d_in[11];
    const float* Wl1   = (const float*)d_in[12];
    const float* bl1   = (const float*)d_in[13];
    const float* Wd    = (const float*)d_in[14];
    const float* bd    = (const float*)d_in[15];

    const int B  = in_sizes[0];
    const int K0 = in_sizes[2] / HID;
    const int T  = in_sizes[1] / K0;

    __half *feat16, *x1h, *x2h, *xp16, *We0h, *We1h, *Wihp, *Whhp, *h0, *h1;
    float *bsum, *hf, *t0, *t1;
    int *starts;
    cudaGetSymbolAddress((void**)&feat16, g_feat16);
    cudaGetSymbolAddress((void**)&x1h,   g_x1h);
    cudaGetSymbolAddress((void**)&x2h,   g_x2h);
    cudaGetSymbolAddress((void**)&xp16,  g_xp16);
    cudaGetSymbolAddress((void**)&We0h,  g_We0h);
    cudaGetSymbolAddress((void**)&We1h,  g_We1h);
    cudaGetSymbolAddress((void**)&Wihp,  g_Wihp);
    cudaGetSymbolAddress((void**)&Whhp,  g_Whhp);
    cudaGetSymbolAddress((void**)&bsum,  g_bsum);
    cudaGetSymbolAddress((void**)&h0,    g_h0);
    cudaGetSymbolAddress((void**)&h1,    g_h1);
    cudaGetSymbolAddress((void**)&hf,    g_hf);
    cudaGetSymbolAddress((void**)&t0,    g_t0);
    cudaGetSymbolAddress((void**)&t1,    g_t1);
    cudaGetSymbolAddress((void**)&starts, g_starts);

    cudaFuncSetAttribute(lstm_persist, cudaFuncAttributeMaxDynamicSharedMemorySize, LSTM_SMEM);
    cudaFuncSetAttribute(hgemm_nt<true, true>,  cudaFuncAttributeMaxDynamicSharedMemorySize, HG_SMEM);
    cudaFuncSetAttribute(hgemm_nt<false, false>, cudaFuncAttributeMaxDynamicSharedMemorySize, HG_SMEM);

    // launch 1: starts scan
    scan_starts_kernel<<<1, BMAX>>>(sizes, starts, B);

    // launch 2: merged prep
    const int nb_feat = (T * K0PAD + 255) / 256;
    const int prep_blocks = nb_feat + 384 + 1024 + 4096 + 4096 + 8 + 2048;
    prep_kernel<<<prep_blocks, 256>>>(feat, We0, We1, Wih, Whh, bih, bhh, T, K0, nb_feat);

    // launches 3-5: encoder + xproj (R12 streamed GEMM, 2 CTAs/SM)
    const int mblkT = (T + 127) / 128;
    hgemm_nt<true, true><<<dim3(HID / 128, mblkT), 256, HG_SMEM>>>(feat16, We0h, be0, x1h, T, HID, K0PAD);
    hgemm_nt<true, true><<<dim3(HID / 128, mblkT), 256, HG_SMEM>>>(x1h, We1h, be1, x2h, T, HID, HID);
    hgemm_nt<false, false><<<dim3(GATES / 128, mblkT), 256, HG_SMEM>>>(x2h, Wihp, nullptr, xp16, T, GATES, HID);

    // launch 6: persistent LSTM (pair-balanced epilogue)
    lstm_persist<<<NCTA, LNT, LSTM_SMEM>>>(Whhp, xp16, bsum, starts, sizes, h0, h1, hf);

    // tail
    gemm_nt_kernel<<<dim3(HID / BN, B / BM), 256>>>(hf, Wl0, bl0, hf, t0, B, HID, HID);
    gemm_nt_kernel<<<dim3(HID / BN, B / BM), 256>>>(t0, Wl1, bl1, t0, t1, B, HID, HID);
    decoder_kernel<<<(B * 32 + 255) / 256, 256>>>(t1, Wd, bd, (float*)d_out, B);
}

// round 16
// speedup vs baseline: 1.2362x; 1.0455x over previous
#include <cuda_runtime.h>
#include <cuda_fp16.h>
#include <math.h>
#include <stdint.h>

// ---------------------------------------------------------------------------
// Problem constants
// ---------------------------------------------------------------------------
#define HID    512
#define GATES  2048
#define MAXLEN 128
#define BMAX   1024
#define TMAX   (BMAX * 127)
#define K0PAD  192
#define NCTA   128         // persistent LSTM grid (16 nblk x 8 mblk)
#define NGRP   8
#define GRPSZ  16

// LSTM chunking
#define CH        64
#define NKT       8
#define AS_STRIDE 72
#define AS_STAGE  (128 * AS_STRIDE)

// hgemm: 64-col K chunks, 3 stages
#define HG_STRIDE 72
#define HG_STAGE  (128 * HG_STRIDE)
#define HG_SMEM   (6 * HG_STAGE * 2)

// ---------------------------------------------------------------------------
// Scratch
// ---------------------------------------------------------------------------
__device__ __half g_feat16[(size_t)TMAX * K0PAD];
__device__ __half g_x1h  [(size_t)TMAX * HID];
__device__ __half g_x2h  [(size_t)TMAX * HID];
__device__ __half g_xp16 [(size_t)TMAX * GATES];
__device__ __half g_We0h [HID * K0PAD];
__device__ __half g_We1h [HID * HID];
__device__ __half g_Wihp [GATES * HID];     // gate-interleaved rows
__device__ __half g_Whhp [GATES * HID];     // gate-interleaved rows
__device__ __half g_Wl0h [HID * HID];
__device__ __half g_Wl1h [HID * HID];
__device__ float  g_bsum [GATES];           // gate-interleaved bih+bhh
__device__ __half g_h0   [BMAX * HID];
__device__ __half g_h1   [BMAX * HID];
__device__ float  g_hf   [BMAX * HID];
__device__ float  g_t0   [BMAX * HID];
__device__ __half g_t0h  [BMAX * HID];
__device__ float  g_t1   [BMAX * HID];
__device__ int    g_starts[BMAX];
// per-CTA dataflow flags (one 128B line each), single wait point per step
__device__ volatile unsigned g_flagB[NGRP][GRPSZ][32];

// ---------------------------------------------------------------------------
// Helpers
// ---------------------------------------------------------------------------
__device__ __forceinline__ uint32_t smem_u32(const void* p) {
    return (uint32_t)__cvta_generic_to_shared(p);
}
__device__ __forceinline__ void cp_async16(void* dst, const void* src, bool pred) {
    uint32_t d = smem_u32(dst);
    int sz = pred ? 16 : 0;
    asm volatile("cp.async.cg.shared.global [%0], [%1], 16, %2;\n"
                 :: "r"(d), "l"(src), "r"(sz));
}
__device__ __forceinline__ void cp_commit() { asm volatile("cp.async.commit_group;\n"); }
template<int N> __device__ __forceinline__ void cp_wait() {
    asm volatile("cp.async.wait_group %0;\n" :: "n"(N));
}
__device__ __forceinline__ void ldm_x4(uint32_t addr, uint32_t& r0, uint32_t& r1,
                                       uint32_t& r2, uint32_t& r3) {
    asm volatile("ldmatrix.sync.aligned.m8n8.x4.shared.b16 {%0,%1,%2,%3}, [%4];"
                 : "=r"(r0), "=r"(r1), "=r"(r2), "=r"(r3) : "r"(addr));
}
__device__ __forceinline__ void mma16816(float* c, const uint32_t* a, const uint32_t* b) {
    asm volatile("mma.sync.aligned.m16n8k16.row.col.f32.f16.f16.f32 "
                 "{%0,%1,%2,%3}, {%4,%5,%6,%7}, {%8,%9}, {%0,%1,%2,%3};"
                 : "+f"(c[0]), "+f"(c[1]), "+f"(c[2]), "+f"(c[3])
                 : "r"(a[0]), "r"(a[1]), "r"(a[2]), "r"(a[3]), "r"(b[0]), "r"(b[1]));
}
__device__ __forceinline__ float fast_sigmoid(float x) {
    return __fdividef(1.f, 1.f + __expf(-x));
}
__device__ __forceinline__ float fast_tanh(float x) {
    float xc = fminf(fmaxf(x, -8.f), 8.f);
    float e = __expf(2.f * xc);
    return __fdividef(e - 1.f, e + 1.f);
}

// ---------------------------------------------------------------------------
// setup: scan (launch 1) + merged prep (launch 2)
// ---------------------------------------------------------------------------
__global__ void scan_starts_kernel(const int* __restrict__ sizes, int* __restrict__ starts, int B) {
    __shared__ int s[BMAX];
    int tid = threadIdx.x;
    if (tid < B) s[tid] = sizes[tid];
    __syncthreads();
    if (tid == 0) {
        int acc = 0;
        for (int i = 0; i < B; i++) { starts[i] = acc; acc += s[i]; }
    }
}

__global__ void prep_kernel(const float* __restrict__ feat,
                            const float* __restrict__ We0, const float* __restrict__ We1,
                            const float* __restrict__ Wih, const float* __restrict__ Whh,
                            const float* __restrict__ bih, const float* __restrict__ bhh,
                            const float* __restrict__ Wl0, const float* __restrict__ Wl1,
                            int T, int K0, int nb_feat)
{
    int b = blockIdx.x, tid = threadIdx.x;
    if (b < nb_feat) {
        int i = b * 256 + tid;
        if (i < T * K0PAD) {
            int r = i / K0PAD, c = i - r * K0PAD;
            g_feat16[i] = __float2half(c < K0 ? feat[(size_t)r * K0 + c] : 0.f);
        }
        return;
    }
    b -= nb_feat;
    if (b < 384) {
        int i = b * 256 + tid;
        int r = i / K0PAD, c = i - r * K0PAD;
        g_We0h[i] = __float2half(c < K0 ? We0[(size_t)r * K0 + c] : 0.f);
        return;
    }
    b -= 384;
    if (b < 1024) {
        int i = b * 256 + tid;
        g_We1h[i] = __float2half(We1[i]);
        return;
    }
    b -= 1024;
    if (b < 4096) {
        int i = b * 256 + tid;
        int r = i >> 9, c = i & 511;
        int g = r >> 9, hid = r & 511;
        g_Wihp[(size_t)(hid * 4 + g) * HID + c] = __float2half(Wih[i]);
        return;
    }
    b -= 4096;
    if (b < 4096) {
        int i = b * 256 + tid;
        int r = i >> 9, c = i & 511;
        int g = r >> 9, hid = r & 511;
        g_Whhp[(size_t)(hid * 4 + g) * HID + c] = __float2half(Whh[i]);
        return;
    }
    b -= 4096;
    if (b < 8) {
        int o = b * 256 + tid;
        int hid = o >> 2, g = o & 3;
        g_bsum[o] = bih[g * HID + hid] + bhh[g * HID + hid];
        return;
    }
    b -= 8;
    if (b < 16) {                         // zero dataflow flags (graph-replay safe)
        int i = b * 256 + tid;
        if (i < NGRP * GRPSZ * 32)
            (&g_flagB[0][0][0])[i] = 0;
        return;
    }
    b -= 16;
    if (b < 1024) {                       // Wl0 -> fp16
        int i = b * 256 + tid;
        g_Wl0h[i] = __float2half(Wl0[i]);
        return;
    }
    b -= 1024;
    if (b < 1024) {                       // Wl1 -> fp16
        int i = b * 256 + tid;
        g_Wl1h[i] = __float2half(Wl1[i]);
        return;
    }
    b -= 1024;
    {
        int i = b * 256 + tid;
        g_h0[i] = __float2half(0.f);
    }
}

// ---------------------------------------------------------------------------
// fp16 NT GEMM: 64-col K chunks, ONE sync per chunk, 3-stage ring, 2 CTAs/SM.
// RESID variant: C = relu(A@B^T + bias) + Rres (fp32 master Cf, optional fp16
// shadow Ch). Non-RESID: fp16 output to Ch.
// ---------------------------------------------------------------------------
template<bool RELU, bool HAS_BIAS, bool RESID>
__global__ __launch_bounds__(256, 2)
void hgemm_nt(const __half* __restrict__ A, const __half* __restrict__ B,
              const float* __restrict__ bias, const float* __restrict__ Rres,
              float* __restrict__ Cf, __half* __restrict__ Ch,
              int M, int N, int K)
{
    extern __shared__ char smem[];
    __half* As = (__half*)smem;                       // [3][128][72]
    __half* Bs = (__half*)(smem + 3 * HG_STAGE * 2);  // [3][128][72]

    const int m0 = blockIdx.y * 128;
    const int n0 = blockIdx.x * 128;
    const int tid = threadIdx.x;
    const int warp = tid >> 5, lane = tid & 31;
    const int wm = (warp & 3) * 32;
    const int wn = (warp >> 2) * 64;

    float acc[2][8][4];
    #pragma unroll
    for (int i = 0; i < 2; i++)
        #pragma unroll
        for (int j = 0; j < 8; j++)
            #pragma unroll
            for (int q = 0; q < 4; q++) acc[i][j][q] = 0.f;

    const int KT = K >> 6;

    auto load_chunk = [&](int c, int s) {
        const int k0 = c << 6;
        for (int i = tid; i < 1024; i += 256) {
            int r = i >> 3, ch = i & 7;
            int gm = m0 + r;
            bool p = gm < M;
            cp_async16(&As[s * HG_STAGE + r * HG_STRIDE + ch * 8],
                       A + (size_t)(p ? gm : 0) * K + k0 + ch * 8, p);
        }
        for (int i = tid; i < 1024; i += 256) {
            int r = i >> 3, ch = i & 7;
            cp_async16(&Bs[s * HG_STAGE + r * HG_STRIDE + ch * 8],
                       B + (size_t)(n0 + r) * K + k0 + ch * 8, true);
        }
        cp_commit();
    };

    load_chunk(0, 0);
    if (KT > 1) load_chunk(1, 1);

    for (int kt = 0; kt < KT; kt++) {
        if (kt + 1 < KT) cp_wait<1>(); else cp_wait<0>();
        __syncthreads();
        if (kt + 2 < KT) load_chunk(kt + 2, (kt + 2) % 3);

        const int stage = kt % 3;
        #pragma unroll
        for (int s = 0; s < 4; s++) {
            uint32_t afrag[2][4];
            #pragma unroll
            for (int mi = 0; mi < 2; mi++) {
                int r = wm + mi * 16 + (lane & 15);
                int c = s * 16 + (lane >> 4) * 8;
                ldm_x4(smem_u32(&As[stage * HG_STAGE + r * HG_STRIDE + c]),
                       afrag[mi][0], afrag[mi][1], afrag[mi][2], afrag[mi][3]);
            }
            uint32_t bfrag[8][2];
            #pragma unroll
            for (int njp = 0; njp < 4; njp++) {
                int g = lane >> 3;
                int nrow = wn + njp * 16 + (g >> 1) * 8 + (lane & 7);
                int c = s * 16 + (g & 1) * 8;
                uint32_t r0, r1, r2, r3;
                ldm_x4(smem_u32(&Bs[stage * HG_STAGE + nrow * HG_STRIDE + c]), r0, r1, r2, r3);
                bfrag[njp * 2][0] = r0; bfrag[njp * 2][1] = r1;
                bfrag[njp * 2 + 1][0] = r2; bfrag[njp * 2 + 1][1] = r3;
            }
            #pragma unroll
            for (int mi = 0; mi < 2; mi++)
                #pragma unroll
                for (int ni = 0; ni < 8; ni++)
                    mma16816(acc[mi][ni], afrag[mi], bfrag[ni]);
        }
    }

    const int r_lo = lane >> 2;
    const int cpair = (lane & 3) * 2;
    #pragma unroll
    for (int mi = 0; mi < 2; mi++) {
        #pragma unroll
        for (int hr = 0; hr < 2; hr++) {
            int gr = m0 + wm + mi * 16 + r_lo + hr * 8;
            if (gr >= M) continue;
            #pragma unroll
            for (int ni = 0; ni < 8; ni++) {
                int gc = n0 + wn + ni * 8 + cpair;
                float v0 = acc[mi][ni][hr * 2 + 0];
                float v1 = acc[mi][ni][hr * 2 + 1];
                if (HAS_BIAS) { v0 += bias[gc]; v1 += bias[gc + 1]; }
                if (RELU) { v0 = fmaxf(v0, 0.f); v1 = fmaxf(v1, 0.f); }
                if (RESID) {
                    v0 += Rres[(size_t)gr * N + gc];
                    v1 += Rres[(size_t)gr * N + gc + 1];
                    *reinterpret_cast<float2*>(Cf + (size_t)gr * N + gc) = make_float2(v0, v1);
                    if (Ch) {
                        __half2 hv;
                        hv.x = __float2half(v0); hv.y = __float2half(v1);
                        *reinterpret_cast<__half2*>(Ch + (size_t)gr * N + gc) = hv;
                    }
                } else {
                    __half2 hv;
                    hv.x = __float2half(v0); hv.y = __float2half(v1);
                    *reinterpret_cast<__half2*>(Ch + (size_t)gr * N + gc) = hv;
                }
            }
        }
    }
}

// ---------------------------------------------------------------------------
// Persistent LSTM: 512 threads (16 warps, 32x32 warp tiles), pair-balanced
// fast-math epilogue, parallel-flag group barrier (single wait point/step).
// ---------------------------------------------------------------------------
#define LSTM_SMEM 212480
#define LNT 512

__device__ __forceinline__ void group_sync(int grp, int myj, unsigned tgt) {
    __syncthreads();                   // all h stores of this CTA done
    if (threadIdx.x == 0) {
        __threadfence();
        g_flagB[grp][myj][0] = tgt;    // release
    }
    if (threadIdx.x < GRPSZ) {
        while (g_flagB[grp][threadIdx.x][0] < tgt) { }
    }
    __syncthreads();
}

__global__ __launch_bounds__(LNT, 1)
void lstm_persist(const __half* __restrict__ Whp, const __half* __restrict__ xp,
                  const float* __restrict__ bsum,
                  const int* __restrict__ starts, const int* __restrict__ sizes,
                  __half* __restrict__ hbuf0, __half* __restrict__ hbuf1,
                  float* __restrict__ hf)
{
    extern __shared__ char smem[];
    __half* WhS = (__half*)(smem);
    __half* AS  = (__half*)(smem + 133120);
    __half* xpS = (__half*)(smem + 169984);
    float*  bsS = (float*) (smem + 202752);
    int*    stS = (int*)   (smem + 203264);
    int*    szS = (int*)   (smem + 203776);
    __half* hS  = (__half*)(smem + 204288);

    const int tid  = threadIdx.x;
    const int warp = tid >> 5, lane = tid & 31;
    const int nblk = blockIdx.x & 15, mblk = blockIdx.x >> 4;
    const int n0 = nblk * 128, m0 = mblk * 128;
    const int wm = (warp & 3) * 32;
    const int wn = (warp >> 2) * 32;

    for (int i = tid; i < 128 * 64; i += LNT) {
        int r = i >> 6, ch = i & 63;
        cp_async16(&WhS[r * 520 + ch * 8], Whp + (size_t)(n0 + r) * HID + ch * 8, true);
    }
    cp_commit();
    for (int i = tid; i < 128; i += LNT) {
        bsS[i] = bsum[n0 + i];
        stS[i] = starts[m0 + i];
        szS[i] = sizes[m0 + i];
    }
    cp_wait<0>();
    __syncthreads();

    float creg[2][2][2];
    #pragma unroll
    for (int mi = 0; mi < 2; mi++)
        #pragma unroll
        for (int hr = 0; hr < 2; hr++)
            #pragma unroll
            for (int q = 0; q < 2; q++) creg[mi][hr][q] = 0.f;

    for (int i = tid; i < 2048; i += LNT) {
        int rl = i >> 4, ch = i & 15;
        bool pv = 0 < szS[rl];
        cp_async16(&xpS[rl * 128 + ch * 8], xp + (size_t)stS[rl] * GATES + n0 + ch * 8, pv);
    }
    for (int i = tid; i < 1024; i += LNT) {
        int r = i >> 3, ch = i & 7;
        cp_async16(&AS[r * AS_STRIDE + ch * 8], hbuf0 + (size_t)(m0 + r) * HID + ch * 8, true);
    }
    cp_commit();

    const int  hlq  = (lane & 3) >> 1;
    const int  rbase = wm + (lane >> 2);
    const bool oddl = (lane & 1) != 0;
    const int  hbase = wn >> 2;

    for (int t = 0; t < MAXLEN; t++) {
        const __half* hA = (t & 1) ? hbuf1 : hbuf0;
        __half*       hN = (t & 1) ? hbuf0 : hbuf1;

        float acc[2][4][4];
        #pragma unroll
        for (int mi = 0; mi < 2; mi++)
            #pragma unroll
            for (int ni = 0; ni < 4; ni++)
                #pragma unroll
                for (int q = 0; q < 4; q++) acc[mi][ni][q] = 0.f;

        for (int kt = 0; kt < NKT; kt++) {
            cp_wait<0>();
            __syncthreads();
            if (kt < NKT - 1) {
                const int k0 = (kt + 1) * CH;
                const int stg = (kt + 1) & 1;
                for (int i = tid; i < 1024; i += LNT) {
                    int r = i >> 3, ch = i & 7;
                    cp_async16(&AS[stg * AS_STAGE + r * AS_STRIDE + ch * 8],
                               hA + (size_t)(m0 + r) * HID + k0 + ch * 8, true);
                }
                cp_commit();
            }
            const int stage = kt & 1;
            #pragma unroll
            for (int s = 0; s < 4; s++) {
                const int ks = kt * 4 + s;
                uint32_t afrag[2][4];
                #pragma unroll
                for (int mi = 0; mi < 2; mi++) {
                    int r = wm + mi * 16 + (lane & 15);
                    int c = s * 16 + (lane >> 4) * 8;
                    ldm_x4(smem_u32(&AS[stage * AS_STAGE + r * AS_STRIDE + c]),
                           afrag[mi][0], afrag[mi][1], afrag[mi][2], afrag[mi][3]);
                }
                uint32_t bfrag[4][2];
                #pragma unroll
                for (int njp = 0; njp < 2; njp++) {
                    int g = lane >> 3;
                    int nrow = wn + njp * 16 + (g >> 1) * 8 + (lane & 7);
                    int c = ks * 16 + (g & 1) * 8;
                    uint32_t r0, r1, r2, r3;
                    ldm_x4(smem_u32(&WhS[nrow * 520 + c]), r0, r1, r2, r3);
                    bfrag[njp * 2][0] = r0; bfrag[njp * 2][1] = r1;
                    bfrag[njp * 2 + 1][0] = r2; bfrag[njp * 2 + 1][1] = r3;
                }
                #pragma unroll
                for (int mi = 0; mi < 2; mi++)
                    #pragma unroll
                    for (int ni = 0; ni < 4; ni++)
                        mma16816(acc[mi][ni], afrag[mi], bfrag[ni]);
            }
        }

        // ---- pair-balanced fused LSTM epilogue ----
        #pragma unroll
        for (int mi = 0; mi < 2; mi++) {
            #pragma unroll
            for (int hr = 0; hr < 2; hr++) {
                const int rl = rbase + mi * 16 + hr * 8;
                #pragma unroll
                for (int ni2 = 0; ni2 < 2; ni2++) {
                    float va0 = acc[mi][ni2][hr * 2 + 0];
                    float va1 = acc[mi][ni2][hr * 2 + 1];
                    float vb0 = acc[mi][ni2 + 2][hr * 2 + 0];
                    float vb1 = acc[mi][ni2 + 2][hr * 2 + 1];
                    float s0 = oddl ? va0 : vb0;
                    float s1 = oddl ? va1 : vb1;
                    float r0 = __shfl_xor_sync(0xffffffffu, s0, 1);
                    float r1 = __shfl_xor_sync(0xffffffffu, s1, 1);
                    float gi = oddl ? r0 : va0;
                    float gf = oddl ? r1 : va1;
                    float gg = oddl ? vb0 : r0;
                    float go = oddl ? vb1 : r1;
                    const int myni = oddl ? (ni2 + 2) : ni2;
                    const int hl = hbase + myni * 2 + hlq;
                    gi += bsS[hl * 4 + 0];
                    gf += bsS[hl * 4 + 1];
                    gg += bsS[hl * 4 + 2];
                    go += bsS[hl * 4 + 3];
                    if (t < szS[rl]) {
                        uint2 xv = *reinterpret_cast<const uint2*>(&xpS[rl * 128 + hl * 4]);
                        __half2 x01 = *reinterpret_cast<__half2*>(&xv.x);
                        __half2 x23 = *reinterpret_cast<__half2*>(&xv.y);
                        gi += __half2float(x01.x);
                        gf += __half2float(x01.y);
                        gg += __half2float(x23.x);
                        go += __half2float(x23.y);
                    }
                    float is = fast_sigmoid(gi);
                    float fs = fast_sigmoid(gf);
                    float gt = fast_tanh(gg);
                    float os = fast_sigmoid(go);
                    float cn = fs * creg[mi][hr][ni2] + is * gt;
                    creg[mi][hr][ni2] = cn;
                    hS[rl * 32 + hl] = __float2half(os * fast_tanh(cn));
                }
            }
        }
        __syncthreads();
        for (int i = tid; i < 512; i += LNT) {
            int r = i >> 2, ch = i & 3;
            *reinterpret_cast<uint4*>(hN + (size_t)(m0 + r) * HID + nblk * 32 + ch * 8) =
                *reinterpret_cast<const uint4*>(&hS[r * 32 + ch * 8]);
        }
        if (t == MAXLEN - 1) {
            for (int i = tid; i < 4096; i += LNT) {
                int r = i >> 5, cch = i & 31;
                hf[(size_t)(m0 + r) * HID + nblk * 32 + cch] = __half2float(hS[r * 32 + cch]);
            }
            break;
        }

        // xp(t+1) prefetch (independent of h)
        for (int i = tid; i < 2048; i += LNT) {
            int rl = i >> 4, ch = i & 15;
            bool pv = (t + 1) < szS[rl];
            cp_async16(&xpS[rl * 128 + ch * 8],
                       xp + (size_t)(stS[rl] + t + 1) * GATES + n0 + ch * 8, pv);
        }
        cp_commit();

        group_sync(mblk, nblk, (unsigned)(t + 1));

        for (int i = tid; i < 1024; i += LNT) {
            int r = i >> 3, ch = i & 7;
            cp_async16(&AS[r * AS_STRIDE + ch * 8], hN + (size_t)(m0 + r) * HID + ch * 8, true);
        }
        cp_commit();
    }
}

// ---------------------------------------------------------------------------
// decoder
// ---------------------------------------------------------------------------
__global__ void decoder_kernel(const float* __restrict__ X, const float* __restrict__ Wd,
                               const float* __restrict__ bd, float* __restrict__ out, int B)
{
    int warp = (blockIdx.x * blockDim.x + threadIdx.x) >> 5;
    int lane = threadIdx.x & 31;
    if (warp >= B) return;
    const float4* row = reinterpret_cast<const float4*>(X + (size_t)warp * HID);
    const float4* w = reinterpret_cast<const float4*>(Wd);
    float s = 0.f;
    #pragma unroll
    for (int i = lane; i < HID / 4; i += 32) {
        float4 a = row[i], bw = w[i];
        s += a.x * bw.x + a.y * bw.y + a.z * bw.z + a.w * bw.w;
    }
    #pragma unroll
    for (int o = 16; o > 0; o >>= 1) s += __shfl_down_sync(0xffffffffu, s, o);
    if (lane == 0) out[warp] = s + bd[0];
}

// ---------------------------------------------------------------------------
// Launch
// ---------------------------------------------------------------------------
extern "C" void kernel_launch(void* const* d_in, const int* in_sizes, int n_in,
                              void* d_out, int out_size)
{
    const int*   sizes = (const int*)  d_in[0];
    const float* feat  = (const float*)d_in[1];
    const float* We0   = (const float*)d_in[2];
    const float* be0   = (const float*)d_in[3];
    const float* We1   = (const float*)d_in[4];
    const float* be1   = (const float*)d_in[5];
    const float* Wih   = (const float*)d_in[6];
    const float* bih   = (const float*)d_in[7];
    const float* Whh   = (const float*)d_in[8];
    const float* bhh   = (const float*)d_in[9];
    const float* Wl0   = (const float*)d_in[10];
    const float* bl0   = (const float*)d_in[11];
    const float* Wl1   = (const float*)d_in[12];
    const float* bl1   = (const float*)d_in[13];
    const float* Wd    = (const float*)d_in[14];
    const float* bd    = (const float*)d_in[15];

    const int B  = in_sizes[0];
    const int K0 = in_sizes[2] / HID;
    const int T  = in_sizes[1] / K0;

    __half *feat16, *x1h, *x2h, *xp16, *We0h, *We1h, *Wihp, *Whhp, *Wl0h, *Wl1h;
    __half *h0, *h1, *t0h;
    float *bsum, *hf, *t0, *t1;
    int *starts;
    cudaGetSymbolAddress((void**)&feat16, g_feat16);
    cudaGetSymbolAddress((void**)&x1h,   g_x1h);
    cudaGetSymbolAddress((void**)&x2h,   g_x2h);
    cudaGetSymbolAddress((void**)&xp16,  g_xp16);
    cudaGetSymbolAddress((void**)&We0h,  g_We0h);
    cudaGetSymbolAddress((void**)&We1h,  g_We1h);
    cudaGetSymbolAddress((void**)&Wihp,  g_Wihp);
    cudaGetSymbolAddress((void**)&Whhp,  g_Whhp);
    cudaGetSymbolAddress((void**)&Wl0h,  g_Wl0h);
    cudaGetSymbolAddress((void**)&Wl1h,  g_Wl1h);
    cudaGetSymbolAddress((void**)&bsum,  g_bsum);
    cudaGetSymbolAddress((void**)&h0,    g_h0);
    cudaGetSymbolAddress((void**)&h1,    g_h1);
    cudaGetSymbolAddress((void**)&hf,    g_hf);
    cudaGetSymbolAddress((void**)&t0,    g_t0);
    cudaGetSymbolAddress((void**)&t0h,   g_t0h);
    cudaGetSymbolAddress((void**)&t1,    g_t1);
    cudaGetSymbolAddress((void**)&starts, g_starts);

    cudaFuncSetAttribute(lstm_persist, cudaFuncAttributeMaxDynamicSharedMemorySize, LSTM_SMEM);
    cudaFuncSetAttribute(hgemm_nt<true, true, false>,   cudaFuncAttributeMaxDynamicSharedMemorySize, HG_SMEM);
    cudaFuncSetAttribute(hgemm_nt<false, false, false>, cudaFuncAttributeMaxDynamicSharedMemorySize, HG_SMEM);
    cudaFuncSetAttribute(hgemm_nt<true, true, true>,    cudaFuncAttributeMaxDynamicSharedMemorySize, HG_SMEM);

    // launch 1: starts scan
    scan_starts_kernel<<<1, BMAX>>>(sizes, starts, B);

    // launch 2: merged prep
    const int nb_feat = (T * K0PAD + 255) / 256;
    const int prep_blocks = nb_feat + 384 + 1024 + 4096 + 4096 + 8 + 16 + 1024 + 1024 + 2048;
    prep_kernel<<<prep_blocks, 256>>>(feat, We0, We1, Wih, Whh, bih, bhh, Wl0, Wl1, T, K0, nb_feat);

    // launches 3-5: encoder + xproj
    const int mblkT = (T + 127) / 128;
    hgemm_nt<true, true, false><<<dim3(HID / 128, mblkT), 256, HG_SMEM>>>(
        feat16, We0h, be0, nullptr, nullptr, x1h, T, HID, K0PAD);
    hgemm_nt<true, true, false><<<dim3(HID / 128, mblkT), 256, HG_SMEM>>>(
        x1h, We1h, be1, nullptr, nullptr, x2h, T, HID, HID);
    hgemm_nt<false, false, false><<<dim3(GATES / 128, mblkT), 256, HG_SMEM>>>(
        x2h, Wihp, nullptr, nullptr, nullptr, xp16, T, GATES, HID);

    // launch 6: persistent LSTM (parallel-flag barrier)
    lstm_persist<<<NCTA, LNT, LSTM_SMEM>>>(Whhp, xp16, bsum, starts, sizes, h0, h1, hf);

    // tail: fp16 tensor-core residual MLPs (final fp16 h is in h0)
    hgemm_nt<true, true, true><<<dim3(HID / 128, B / 128), 256, HG_SMEM>>>(
        h0, Wl0h, bl0, hf, t0, t0h, B, HID, HID);
    hgemm_nt<true, true, true><<<dim3(HID / 128, B / 128), 256, HG_SMEM>>>(
        t0h, Wl1h, bl1, t0, t1, nullptr, B, HID, HID);
    decoder_kernel<<<(B * 32 + 255) / 256, 256>>>(t1, Wd, bd, (float*)d_out, B);
}

// round 17
// speedup vs baseline: 1.2905x; 1.0439x over previous
#include <cuda_runtime.h>
#include <cuda_fp16.h>
#include <math.h>
#include <stdint.h>

// ---------------------------------------------------------------------------
// Problem constants
// ---------------------------------------------------------------------------
#define HID    512
#define GATES  2048
#define MAXLEN 128
#define BMAX   1024
#define TMAX   (BMAX * 127)
#define K0PAD  192
#define NCTA   128         // persistent LSTM grid (16 nblk x 8 mblk)
#define NGRP   8
#define GRPSZ  16

// LSTM chunking
#define CH        64
#define NKT       8
#define AS_STRIDE 72
#define AS_STAGE  (128 * AS_STRIDE)

// hgemm: 64-col K chunks, 3 stages
#define HG_STRIDE 72
#define HG_STAGE  (128 * HG_STRIDE)
#define HG_SMEM   (6 * HG_STAGE * 2)

// ---------------------------------------------------------------------------
// Scratch
// ---------------------------------------------------------------------------
__device__ __half g_feat16[(size_t)TMAX * K0PAD];
__device__ __half g_x1h  [(size_t)TMAX * HID];
__device__ __half g_x2h  [(size_t)TMAX * HID];
__device__ __half g_xp16 [(size_t)TMAX * GATES];
__device__ __half g_We0h [HID * K0PAD];
__device__ __half g_We1h [HID * HID];
__device__ __half g_Wihp [GATES * HID];     // gate-interleaved rows
__device__ __half g_Whhp [GATES * HID];     // gate-interleaved rows
__device__ __half g_Wl0h [HID * HID];
__device__ __half g_Wl1h [HID * HID];
__device__ float  g_bsum [GATES];           // gate-interleaved bih+bhh
__device__ __half g_h0   [BMAX * HID];
__device__ __half g_h1   [BMAX * HID];
__device__ float  g_t0   [BMAX * HID];
__device__ __half g_t0h  [BMAX * HID];
__device__ float  g_t1   [BMAX * HID];
__device__ int    g_starts[BMAX];
// per-CTA dataflow flags (one 128B line each), single wait point per step
__device__ volatile unsigned g_flagB[NGRP][GRPSZ][32];

// ---------------------------------------------------------------------------
// Helpers
// ---------------------------------------------------------------------------
__device__ __forceinline__ uint32_t smem_u32(const void* p) {
    return (uint32_t)__cvta_generic_to_shared(p);
}
__device__ __forceinline__ void cp_async16(void* dst, const void* src, bool pred) {
    uint32_t d = smem_u32(dst);
    int sz = pred ? 16 : 0;
    asm volatile("cp.async.cg.shared.global [%0], [%1], 16, %2;\n"
                 :: "r"(d), "l"(src), "r"(sz));
}
__device__ __forceinline__ void cp_commit() { asm volatile("cp.async.commit_group;\n"); }
template<int N> __device__ __forceinline__ void cp_wait() {
    asm volatile("cp.async.wait_group %0;\n" :: "n"(N));
}
__device__ __forceinline__ void ldm_x4(uint32_t addr, uint32_t& r0, uint32_t& r1,
                                       uint32_t& r2, uint32_t& r3) {
    asm volatile("ldmatrix.sync.aligned.m8n8.x4.shared.b16 {%0,%1,%2,%3}, [%4];"
                 : "=r"(r0), "=r"(r1), "=r"(r2), "=r"(r3) : "r"(addr));
}
__device__ __forceinline__ void mma16816(float* c, const uint32_t* a, const uint32_t* b) {
    asm volatile("mma.sync.aligned.m16n8k16.row.col.f32.f16.f16.f32 "
                 "{%0,%1,%2,%3}, {%4,%5,%6,%7}, {%8,%9}, {%0,%1,%2,%3};"
                 : "+f"(c[0]), "+f"(c[1]), "+f"(c[2]), "+f"(c[3])
                 : "r"(a[0]), "r"(a[1]), "r"(a[2]), "r"(a[3]), "r"(b[0]), "r"(b[1]));
}
__device__ __forceinline__ float fast_sigmoid(float x) {
    return __fdividef(1.f, 1.f + __expf(-x));
}
__device__ __forceinline__ float fast_tanh(float x) {
    float xc = fminf(fmaxf(x, -8.f), 8.f);
    float e = __expf(2.f * xc);
    return __fdividef(e - 1.f, e + 1.f);
}

// ---------------------------------------------------------------------------
// setup: scan (launch 1) + merged vectorized prep (launch 2)
// ---------------------------------------------------------------------------
__global__ void scan_starts_kernel(const int* __restrict__ sizes, int* __restrict__ starts, int B) {
    __shared__ int s[BMAX];
    int tid = threadIdx.x;
    if (tid < B) s[tid] = sizes[tid];
    __syncthreads();
    if (tid == 0) {
        int acc = 0;
        for (int i = 0; i < B; i++) { starts[i] = acc; acc += s[i]; }
    }
}

__global__ void prep_kernel(const float* __restrict__ feat,
                            const float* __restrict__ We0, const float* __restrict__ We1,
                            const float* __restrict__ Wih, const float* __restrict__ Whh,
                            const float* __restrict__ bih, const float* __restrict__ bhh,
                            const float* __restrict__ Wl0, const float* __restrict__ Wl1,
                            int T, int K0, int nb_feat)
{
    int b = blockIdx.x, tid = threadIdx.x;
    if (b < nb_feat) {                       // feat: 4 halves / thread (48 quads/row)
        int i4 = b * 256 + tid;
        int r = i4 / 48, cq = (i4 % 48) * 4;
        if (r < T) {
            __half2 h01, h23;
            if (cq < K0) {
                float4 v = *reinterpret_cast<const float4*>(feat + (size_t)r * K0 + cq);
                h01 = __floats2half2_rn(v.x, v.y);
                h23 = __floats2half2_rn(v.z, v.w);
            } else {
                h01 = __floats2half2_rn(0.f, 0.f);
                h23 = h01;
            }
            __half2* dst = reinterpret_cast<__half2*>(g_feat16 + (size_t)r * K0PAD + cq);
            dst[0] = h01; dst[1] = h23;
        }
        return;
    }
    b -= nb_feat;
    if (b < 96) {                            // We0: 512 x 192 (pad)
        int i4 = b * 256 + tid;
        int r = i4 / 48, cq = (i4 % 48) * 4;
        __half2 h01, h23;
        if (cq < K0) {
            float4 v = *reinterpret_cast<const float4*>(We0 + (size_t)r * K0 + cq);
            h01 = __floats2half2_rn(v.x, v.y);
            h23 = __floats2half2_rn(v.z, v.w);
        } else {
            h01 = __floats2half2_rn(0.f, 0.f);
            h23 = h01;
        }
        __half2* dst = reinterpret_cast<__half2*>(g_We0h + (size_t)r * K0PAD + cq);
        dst[0] = h01; dst[1] = h23;
        return;
    }
    b -= 96;
    if (b < 256) {                           // We1: 512x512
        int i4 = (b * 256 + tid) * 4;
        float4 v = *reinterpret_cast<const float4*>(We1 + i4);
        __half2* dst = reinterpret_cast<__half2*>(g_We1h + i4);
        dst[0] = __floats2half2_rn(v.x, v.y);
        dst[1] = __floats2half2_rn(v.z, v.w);
        return;
    }
    b -= 256;
    if (b < 1024) {                          // Wih row-permute, 4 cols / thread
        int i4 = b * 256 + tid;
        int r = i4 >> 7, c4 = (i4 & 127) * 4;
        int g = r >> 9, hid = r & 511;
        float4 v = *reinterpret_cast<const float4*>(Wih + (size_t)r * HID + c4);
        __half2* dst = reinterpret_cast<__half2*>(g_Wihp + (size_t)(hid * 4 + g) * HID + c4);
        dst[0] = __floats2half2_rn(v.x, v.y);
        dst[1] = __floats2half2_rn(v.z, v.w);
        return;
    }
    b -= 1024;
    if (b < 1024) {                          // Whh row-permute
        int i4 = b * 256 + tid;
        int r = i4 >> 7, c4 = (i4 & 127) * 4;
        int g = r >> 9, hid = r & 511;
        float4 v = *reinterpret_cast<const float4*>(Whh + (size_t)r * HID + c4);
        __half2* dst = reinterpret_cast<__half2*>(g_Whhp + (size_t)(hid * 4 + g) * HID + c4);
        dst[0] = __floats2half2_rn(v.x, v.y);
        dst[1] = __floats2half2_rn(v.z, v.w);
        return;
    }
    b -= 1024;
    if (b < 8) {                             // bsum (gate-interleaved)
        int o = b * 256 + tid;
        int hid = o >> 2, g = o & 3;
        g_bsum[o] = bih[g * HID + hid] + bhh[g * HID + hid];
        return;
    }
    b -= 8;
    if (b < 16) {                            // zero dataflow flags
        int i = b * 256 + tid;
        if (i < NGRP * GRPSZ * 32)
            (&g_flagB[0][0][0])[i] = 0;
        return;
    }
    b -= 16;
    if (b < 256) {                           // Wl0 -> fp16
        int i4 = (b * 256 + tid) * 4;
        float4 v = *reinterpret_cast<const float4*>(Wl0 + i4);
        __half2* dst = reinterpret_cast<__half2*>(g_Wl0h + i4);
        dst[0] = __floats2half2_rn(v.x, v.y);
        dst[1] = __floats2half2_rn(v.z, v.w);
        return;
    }
    b -= 256;
    if (b < 256) {                           // Wl1 -> fp16
        int i4 = (b * 256 + tid) * 4;
        float4 v = *reinterpret_cast<const float4*>(Wl1 + i4);
        __half2* dst = reinterpret_cast<__half2*>(g_Wl1h + i4);
        dst[0] = __floats2half2_rn(v.x, v.y);
        dst[1] = __floats2half2_rn(v.z, v.w);
        return;
    }
    b -= 256;
    {                                        // zero h0: 8 halves / thread
        int i = b * 256 + tid;
        reinterpret_cast<uint4*>(g_h0)[i] = make_uint4(0u, 0u, 0u, 0u);
    }
}

// ---------------------------------------------------------------------------
// fp16 NT GEMM: 64-col K chunks, ONE sync per chunk, 3-stage ring, 2 CTAs/SM.
// RES: 0 = fp16 out only; 1 = +fp32 residual Rf; 2 = +fp16 residual Rh.
// RES!=0 writes fp32 master Cf and optional fp16 shadow Ch.
// ---------------------------------------------------------------------------
template<bool RELU, bool HAS_BIAS, int RES>
__global__ __launch_bounds__(256, 2)
void hgemm_nt(const __half* __restrict__ A, const __half* __restrict__ B,
              const float* __restrict__ bias,
              const float* __restrict__ Rf, const __half* __restrict__ Rh,
              float* __restrict__ Cf, __half* __restrict__ Ch,
              int M, int N, int K)
{
    extern __shared__ char smem[];
    __half* As = (__half*)smem;                       // [3][128][72]
    __half* Bs = (__half*)(smem + 3 * HG_STAGE * 2);  // [3][128][72]

    const int m0 = blockIdx.y * 128;
    const int n0 = blockIdx.x * 128;
    const int tid = threadIdx.x;
    const int warp = tid >> 5, lane = tid & 31;
    const int wm = (warp & 3) * 32;
    const int wn = (warp >> 2) * 64;

    float acc[2][8][4];
    #pragma unroll
    for (int i = 0; i < 2; i++)
        #pragma unroll
        for (int j = 0; j < 8; j++)
            #pragma unroll
            for (int q = 0; q < 4; q++) acc[i][j][q] = 0.f;

    const int KT = K >> 6;

    auto load_chunk = [&](int c, int s) {
        const int k0 = c << 6;
        for (int i = tid; i < 1024; i += 256) {
            int r = i >> 3, ch = i & 7;
            int gm = m0 + r;
            bool p = gm < M;
            cp_async16(&As[s * HG_STAGE + r * HG_STRIDE + ch * 8],
                       A + (size_t)(p ? gm : 0) * K + k0 + ch * 8, p);
        }
        for (int i = tid; i < 1024; i += 256) {
            int r = i >> 3, ch = i & 7;
            cp_async16(&Bs[s * HG_STAGE + r * HG_STRIDE + ch * 8],
                       B + (size_t)(n0 + r) * K + k0 + ch * 8, true);
        }
        cp_commit();
    };

    load_chunk(0, 0);
    if (KT > 1) load_chunk(1, 1);

    for (int kt = 0; kt < KT; kt++) {
        if (kt + 1 < KT) cp_wait<1>(); else cp_wait<0>();
        __syncthreads();
        if (kt + 2 < KT) load_chunk(kt + 2, (kt + 2) % 3);

        const int stage = kt % 3;
        #pragma unroll
        for (int s = 0; s < 4; s++) {
            uint32_t afrag[2][4];
            #pragma unroll
            for (int mi = 0; mi < 2; mi++) {
                int r = wm + mi * 16 + (lane & 15);
                int c = s * 16 + (lane >> 4) * 8;
                ldm_x4(smem_u32(&As[stage * HG_STAGE + r * HG_STRIDE + c]),
                       afrag[mi][0], afrag[mi][1], afrag[mi][2], afrag[mi][3]);
            }
            uint32_t bfrag[8][2];
            #pragma unroll
            for (int njp = 0; njp < 4; njp++) {
                int g = lane >> 3;
                int nrow = wn + njp * 16 + (g >> 1) * 8 + (lane & 7);
                int c = s * 16 + (g & 1) * 8;
                uint32_t r0, r1, r2, r3;
                ldm_x4(smem_u32(&Bs[stage * HG_STAGE + nrow * HG_STRIDE + c]), r0, r1, r2, r3);
                bfrag[njp * 2][0] = r0; bfrag[njp * 2][1] = r1;
                bfrag[njp * 2 + 1][0] = r2; bfrag[njp * 2 + 1][1] = r3;
            }
            #pragma unroll
            for (int mi = 0; mi < 2; mi++)
                #pragma unroll
                for (int ni = 0; ni < 8; ni++)
                    mma16816(acc[mi][ni], afrag[mi], bfrag[ni]);
        }
    }

    const int r_lo = lane >> 2;
    const int cpair = (lane & 3) * 2;
    #pragma unroll
    for (int mi = 0; mi < 2; mi++) {
        #pragma unroll
        for (int hr = 0; hr < 2; hr++) {
            int gr = m0 + wm + mi * 16 + r_lo + hr * 8;
            if (gr >= M) continue;
            #pragma unroll
            for (int ni = 0; ni < 8; ni++) {
                int gc = n0 + wn + ni * 8 + cpair;
                float v0 = acc[mi][ni][hr * 2 + 0];
                float v1 = acc[mi][ni][hr * 2 + 1];
                if (HAS_BIAS) { v0 += bias[gc]; v1 += bias[gc + 1]; }
                if (RELU) { v0 = fmaxf(v0, 0.f); v1 = fmaxf(v1, 0.f); }
                if (RES != 0) {
                    if (RES == 1) {
                        float2 rv = *reinterpret_cast<const float2*>(Rf + (size_t)gr * N + gc);
                        v0 += rv.x; v1 += rv.y;
                    } else {
                        __half2 rh = *reinterpret_cast<const __half2*>(Rh + (size_t)gr * N + gc);
                        v0 += __half2float(rh.x); v1 += __half2float(rh.y);
                    }
                    *reinterpret_cast<float2*>(Cf + (size_t)gr * N + gc) = make_float2(v0, v1);
                    if (Ch) {
                        __half2 hv;
                        hv.x = __float2half(v0); hv.y = __float2half(v1);
                        *reinterpret_cast<__half2*>(Ch + (size_t)gr * N + gc) = hv;
                    }
                } else {
                    __half2 hv;
                    hv.x = __float2half(v0); hv.y = __float2half(v1);
                    *reinterpret_cast<__half2*>(Ch + (size_t)gr * N + gc) = hv;
                }
            }
        }
    }
}

// ---------------------------------------------------------------------------
// Persistent LSTM: 512 threads (16 warps, 32x32 warp tiles), pair-balanced
// fast-math epilogue, parallel-flag barrier with EARLY release (flag published
// right after the h-store; xp prefetch issued between release and wait).
// ---------------------------------------------------------------------------
#define LSTM_SMEM 212480
#define LNT 512

__global__ __launch_bounds__(LNT, 1)
void lstm_persist(const __half* __restrict__ Whp, const __half* __restrict__ xp,
                  const float* __restrict__ bsum,
                  const int* __restrict__ starts, const int* __restrict__ sizes,
                  __half* __restrict__ hbuf0, __half* __restrict__ hbuf1)
{
    extern __shared__ char smem[];
    __half* WhS = (__half*)(smem);
    __half* AS  = (__half*)(smem + 133120);
    __half* xpS = (__half*)(smem + 169984);
    float*  bsS = (float*) (smem + 202752);
    int*    stS = (int*)   (smem + 203264);
    int*    szS = (int*)   (smem + 203776);
    __half* hS  = (__half*)(smem + 204288);

    const int tid  = threadIdx.x;
    const int warp = tid >> 5, lane = tid & 31;
    const int nblk = blockIdx.x & 15, mblk = blockIdx.x >> 4;
    const int n0 = nblk * 128, m0 = mblk * 128;
    const int wm = (warp & 3) * 32;
    const int wn = (warp >> 2) * 32;

    for (int i = tid; i < 128 * 64; i += LNT) {
        int r = i >> 6, ch = i & 63;
        cp_async16(&WhS[r * 520 + ch * 8], Whp + (size_t)(n0 + r) * HID + ch * 8, true);
    }
    cp_commit();
    for (int i = tid; i < 128; i += LNT) {
        bsS[i] = bsum[n0 + i];
        stS[i] = starts[m0 + i];
        szS[i] = sizes[m0 + i];
    }
    cp_wait<0>();
    __syncthreads();

    float creg[2][2][2];
    #pragma unroll
    for (int mi = 0; mi < 2; mi++)
        #pragma unroll
        for (int hr = 0; hr < 2; hr++)
            #pragma unroll
            for (int q = 0; q < 2; q++) creg[mi][hr][q] = 0.f;

    for (int i = tid; i < 2048; i += LNT) {
        int rl = i >> 4, ch = i & 15;
        bool pv = 0 < szS[rl];
        cp_async16(&xpS[rl * 128 + ch * 8], xp + (size_t)stS[rl] * GATES + n0 + ch * 8, pv);
    }
    for (int i = tid; i < 1024; i += LNT) {
        int r = i >> 3, ch = i & 7;
        cp_async16(&AS[r * AS_STRIDE + ch * 8], hbuf0 + (size_t)(m0 + r) * HID + ch * 8, true);
    }
    cp_commit();

    const int  hlq  = (lane & 3) >> 1;
    const int  rbase = wm + (lane >> 2);
    const bool oddl = (lane & 1) != 0;
    const int  hbase = wn >> 2;

    for (int t = 0; t < MAXLEN; t++) {
        const __half* hA = (t & 1) ? hbuf1 : hbuf0;
        __half*       hN = (t & 1) ? hbuf0 : hbuf1;

        float acc[2][4][4];
        #pragma unroll
        for (int mi = 0; mi < 2; mi++)
            #pragma unroll
            for (int ni = 0; ni < 4; ni++)
                #pragma unroll
                for (int q = 0; q < 4; q++) acc[mi][ni][q] = 0.f;

        for (int kt = 0; kt < NKT; kt++) {
            cp_wait<0>();
            __syncthreads();
            if (kt < NKT - 1) {
                const int k0 = (kt + 1) * CH;
                const int stg = (kt + 1) & 1;
                for (int i = tid; i < 1024; i += LNT) {
                    int r = i >> 3, ch = i & 7;
                    cp_async16(&AS[stg * AS_STAGE + r * AS_STRIDE + ch * 8],
                               hA + (size_t)(m0 + r) * HID + k0 + ch * 8, true);
                }
                cp_commit();
            }
            const int stage = kt & 1;
            #pragma unroll
            for (int s = 0; s < 4; s++) {
                const int ks = kt * 4 + s;
                uint32_t afrag[2][4];
                #pragma unroll
                for (int mi = 0; mi < 2; mi++) {
                    int r = wm + mi * 16 + (lane & 15);
                    int c = s * 16 + (lane >> 4) * 8;
                    ldm_x4(smem_u32(&AS[stage * AS_STAGE + r * AS_STRIDE + c]),
                           afrag[mi][0], afrag[mi][1], afrag[mi][2], afrag[mi][3]);
                }
                uint32_t bfrag[4][2];
                #pragma unroll
                for (int njp = 0; njp < 2; njp++) {
                    int g = lane >> 3;
                    int nrow = wn + njp * 16 + (g >> 1) * 8 + (lane & 7);
                    int c = ks * 16 + (g & 1) * 8;
                    uint32_t r0, r1, r2, r3;
                    ldm_x4(smem_u32(&WhS[nrow * 520 + c]), r0, r1, r2, r3);
                    bfrag[njp * 2][0] = r0; bfrag[njp * 2][1] = r1;
                    bfrag[njp * 2 + 1][0] = r2; bfrag[njp * 2 + 1][1] = r3;
                }
                #pragma unroll
                for (int mi = 0; mi < 2; mi++)
                    #pragma unroll
                    for (int ni = 0; ni < 4; ni++)
                        mma16816(acc[mi][ni], afrag[mi], bfrag[ni]);
            }
        }

        // ---- pair-balanced fused LSTM epilogue ----
        #pragma unroll
        for (int mi = 0; mi < 2; mi++) {
            #pragma unroll
            for (int hr = 0; hr < 2; hr++) {
                const int rl = rbase + mi * 16 + hr * 8;
                #pragma unroll
                for (int ni2 = 0; ni2 < 2; ni2++) {
                    float va0 = acc[mi][ni2][hr * 2 + 0];
                    float va1 = acc[mi][ni2][hr * 2 + 1];
                    float vb0 = acc[mi][ni2 + 2][hr * 2 + 0];
                    float vb1 = acc[mi][ni2 + 2][hr * 2 + 1];
                    float s0 = oddl ? va0 : vb0;
                    float s1 = oddl ? va1 : vb1;
                    float r0 = __shfl_xor_sync(0xffffffffu, s0, 1);
                    float r1 = __shfl_xor_sync(0xffffffffu, s1, 1);
                    float gi = oddl ? r0 : va0;
                    float gf = oddl ? r1 : va1;
                    float gg = oddl ? vb0 : r0;
                    float go = oddl ? vb1 : r1;
                    const int myni = oddl ? (ni2 + 2) : ni2;
                    const int hl = hbase + myni * 2 + hlq;
                    gi += bsS[hl * 4 + 0];
                    gf += bsS[hl * 4 + 1];
                    gg += bsS[hl * 4 + 2];
                    go += bsS[hl * 4 + 3];
                    if (t < szS[rl]) {
                        uint2 xv = *reinterpret_cast<const uint2*>(&xpS[rl * 128 + hl * 4]);
                        __half2 x01 = *reinterpret_cast<__half2*>(&xv.x);
                        __half2 x23 = *reinterpret_cast<__half2*>(&xv.y);
                        gi += __half2float(x01.x);
                        gf += __half2float(x01.y);
                        gg += __half2float(x23.x);
                        go += __half2float(x23.y);
                    }
                    float is = fast_sigmoid(gi);
                    float fs = fast_sigmoid(gf);
                    float gt = fast_tanh(gg);
                    float os = fast_sigmoid(go);
                    float cn = fs * creg[mi][hr][ni2] + is * gt;
                    creg[mi][hr][ni2] = cn;
                    hS[rl * 32 + hl] = __float2half(os * fast_tanh(cn));
                }
            }
        }
        __syncthreads();
        // coalesced h store
        for (int i = tid; i < 512; i += LNT) {
            int r = i >> 2, ch = i & 3;
            *reinterpret_cast<uint4*>(hN + (size_t)(m0 + r) * HID + nblk * 32 + ch * 8) =
                *reinterpret_cast<const uint4*>(&hS[r * 32 + ch * 8]);
        }
        if (t == MAXLEN - 1) break;    // final fp16 h lives in hbuf0

        __syncthreads();               // all h stores issued
        if (tid == 0) {
            __threadfence();
            g_flagB[mblk][nblk][0] = (unsigned)(t + 1);   // EARLY release
        }
        // xp(t+1) prefetch (local-only) overlaps the group wait
        for (int i = tid; i < 2048; i += LNT) {
            int rl = i >> 4, ch = i & 15;
            bool pv = (t + 1) < szS[rl];
            cp_async16(&xpS[rl * 128 + ch * 8],
                       xp + (size_t)(stS[rl] + t + 1) * GATES + n0 + ch * 8, pv);
        }
        cp_commit();
        if (tid < GRPSZ) {
            while (g_flagB[mblk][tid][0] < (unsigned)(t + 1)) { }
        }
        __syncthreads();

        for (int i = tid; i < 1024; i += LNT) {
            int r = i >> 3, ch = i & 7;
            cp_async16(&AS[r * AS_STRIDE + ch * 8], hN + (size_t)(m0 + r) * HID + ch * 8, true);
        }
        cp_commit();
    }
}

// ---------------------------------------------------------------------------
// decoder
// ---------------------------------------------------------------------------
__global__ void decoder_kernel(const float* __restrict__ X, const float* __restrict__ Wd,
                               const float* __restrict__ bd, float* __restrict__ out, int B)
{
    int warp = (blockIdx.x * blockDim.x + threadIdx.x) >> 5;
    int lane = threadIdx.x & 31;
    if (warp >= B) return;
    const float4* row = reinterpret_cast<const float4*>(X + (size_t)warp * HID);
    const float4* w = reinterpret_cast<const float4*>(Wd);
    float s = 0.f;
    #pragma unroll
    for (int i = lane; i < HID / 4; i += 32) {
        float4 a = row[i], bw = w[i];
        s += a.x * bw.x + a.y * bw.y + a.z * bw.z + a.w * bw.w;
    }
    #pragma unroll
    for (int o = 16; o > 0; o >>= 1) s += __shfl_down_sync(0xffffffffu, s, o);
    if (lane == 0) out[warp] = s + bd[0];
}

// ---------------------------------------------------------------------------
// Launch
// ---------------------------------------------------------------------------
extern "C" void kernel_launch(void* const* d_in, const int* in_sizes, int n_in,
                              void* d_out, int out_size)
{
    const int*   sizes = (const int*)  d_in[0];
    const float* feat  = (const float*)d_in[1];
    const float* We0   = (const float*)d_in[2];
    const float* be0   = (const float*)d_in[3];
    const float* We1   = (const float*)d_in[4];
    const float* be1   = (const float*)d_in[5];
    const float* Wih   = (const float*)d_in[6];
    const float* bih   = (const float*)d_in[7];
    const float* Whh   = (const float*)d_in[8];
    const float* bhh   = (const float*)d_in[9];
    const float* Wl0   = (const float*)d_in[10];
    const float* bl0   = (const float*)d_in[11];
    const float* Wl1   = (const float*)d_in[12];
    const float* bl1   = (const float*)d_in[13];
    const float* Wd    = (const float*)d_in[14];
    const float* bd    = (const float*)d_in[15];

    const int B  = in_sizes[0];
    const int K0 = in_sizes[2] / HID;
    const int T  = in_sizes[1] / K0;

    __half *feat16, *x1h, *x2h, *xp16, *We0h, *We1h, *Wihp, *Whhp, *Wl0h, *Wl1h;
    __half *h0, *h1, *t0h;
    float *bsum, *t0, *t1;
    int *starts;
    cudaGetSymbolAddress((void**)&feat16, g_feat16);
    cudaGetSymbolAddress((void**)&x1h,   g_x1h);
    cudaGetSymbolAddress((void**)&x2h,   g_x2h);
    cudaGetSymbolAddress((void**)&xp16,  g_xp16);
    cudaGetSymbolAddress((void**)&We0h,  g_We0h);
    cudaGetSymbolAddress((void**)&We1h,  g_We1h);
    cudaGetSymbolAddress((void**)&Wihp,  g_Wihp);
    cudaGetSymbolAddress((void**)&Whhp,  g_Whhp);
    cudaGetSymbolAddress((void**)&Wl0h,  g_Wl0h);
    cudaGetSymbolAddress((void**)&Wl1h,  g_Wl1h);
    cudaGetSymbolAddress((void**)&bsum,  g_bsum);
    cudaGetSymbolAddress((void**)&h0,    g_h0);
    cudaGetSymbolAddress((void**)&h1,    g_h1);
    cudaGetSymbolAddress((void**)&t0,    g_t0);
    cudaGetSymbolAddress((void**)&t0h,   g_t0h);
    cudaGetSymbolAddress((void**)&t1,    g_t1);
    cudaGetSymbolAddress((void**)&starts, g_starts);

    cudaFuncSetAttribute(lstm_persist, cudaFuncAttributeMaxDynamicSharedMemorySize, LSTM_SMEM);
    cudaFuncSetAttribute(hgemm_nt<true, true, 0>,   cudaFuncAttributeMaxDynamicSharedMemorySize, HG_SMEM);
    cudaFuncSetAttribute(hgemm_nt<false, false, 0>, cudaFuncAttributeMaxDynamicSharedMemorySize, HG_SMEM);
    cudaFuncSetAttribute(hgemm_nt<true, true, 1>,   cudaFuncAttributeMaxDynamicSharedMemorySize, HG_SMEM);
    cudaFuncSetAttribute(hgemm_nt<true, true, 2>,   cudaFuncAttributeMaxDynamicSharedMemorySize, HG_SMEM);

    // launch 1: starts scan
    scan_starts_kernel<<<1, BMAX>>>(sizes, starts, B);

    // launch 2: merged vectorized prep
    const int nb_feat = (T * 48 + 255) / 256;
    const int prep_blocks = nb_feat + 96 + 256 + 1024 + 1024 + 8 + 16 + 256 + 256 + 256;
    prep_kernel<<<prep_blocks, 256>>>(feat, We0, We1, Wih, Whh, bih, bhh, Wl0, Wl1, T, K0, nb_feat);

    // launches 3-5: encoder + xproj
    const int mblkT = (T + 127) / 128;
    hgemm_nt<true, true, 0><<<dim3(HID / 128, mblkT), 256, HG_SMEM>>>(
        feat16, We0h, be0, nullptr, nullptr, nullptr, x1h, T, HID, K0PAD);
    hgemm_nt<true, true, 0><<<dim3(HID / 128, mblkT), 256, HG_SMEM>>>(
        x1h, We1h, be1, nullptr, nullptr, nullptr, x2h, T, HID, HID);
    hgemm_nt<false, false, 0><<<dim3(GATES / 128, mblkT), 256, HG_SMEM>>>(
        x2h, Wihp, nullptr, nullptr, nullptr, nullptr, xp16, T, GATES, HID);

    // launch 6: persistent LSTM (early-release parallel-flag barrier)
    lstm_persist<<<NCTA, LNT, LSTM_SMEM>>>(Whhp, xp16, bsum, starts, sizes, h0, h1);

    // tail: fp16 tensor-core residual MLPs (final fp16 h is in h0; residual = h0)
    hgemm_nt<true, true, 2><<<dim3(HID / 128, B / 128), 256, HG_SMEM>>>(
        h0, Wl0h, bl0, nullptr, h0, t0, t0h, B, HID, HID);
    hgemm_nt<true, true, 1><<<dim3(HID / 128, B / 128), 256, HG_SMEM>>>(
        t0h, Wl1h, bl1, t0, nullptr, t1, nullptr, B, HID, HID);
    decoder_kernel<<<(B * 32 + 255) / 256, 256>>>(t1, Wd, bd, (float*)d_out, B);
}